// round 11
// baseline (speedup 1.0000x reference)
#include <cuda_runtime.h>
#include <cuda_bf16.h>
#include <cstdint>

#define NROWS 8192
#define IN_DIM 128
#define HID 64
#define NSPLIT 16
#define JSEG (NROWS / NSPLIT)

typedef unsigned long long ull;

// ---------------- scratch (static device globals; no allocation) ----------------
__device__ __align__(16) float g_struct[NROWS * HID];
__device__ __align__(16) __nv_bfloat16 g_Whh[NROWS * IN_DIM];
__device__ __align__(16) __nv_bfloat16 g_Whl[NROWS * IN_DIM];
__device__ __align__(16) float g_s1[NROWS];
__device__ __align__(16) float g_s2[NROWS];
__device__ __align__(16) float g_A[NROWS];
__device__ __align__(16) float g_B[NROWS];
__device__ __align__(16) float g_C[NROWS];
__device__ __align__(16) float g_D[NROWS];
__device__ unsigned g_s2max_bits = 0u;
__device__ __align__(16) float g_henc[NROWS * HID];
__device__ __align__(16) __nv_bfloat16 g_embh[NROWS * IN_DIM];
__device__ __align__(16) __nv_bfloat16 g_embl[NROWS * IN_DIM];
__device__ __align__(16) float g_pacc[NSPLIT * NROWS * IN_DIM];
__device__ __align__(16) float g_pden[NSPLIT * NROWS];
__device__ __align__(16) uint32_t g_adjbits[NROWS * (NROWS / 32)];   // 8 MB bitmask

// ---------------- helpers ----------------
__device__ __forceinline__ float sigmoidf_(float x) { return 1.0f / (1.0f + __expf(-x)); }

__device__ __forceinline__ unsigned float_key(float f) {
    unsigned b = __float_as_uint(f);
    return (b & 0x80000000u) ? ~b : (b | 0x80000000u);
}
__device__ __forceinline__ float key_float(unsigned k) {
    unsigned b = (k & 0x80000000u) ? (k & 0x7fffffffu) : ~k;
    return __uint_as_float(b);
}
__device__ __forceinline__ uint32_t smem_u32(const void* p) {
    uint32_t a;
    asm("{ .reg .u64 t; cvta.to.shared.u64 t, %1; cvt.u32.u64 %0, t; }" : "=r"(a) : "l"(p));
    return a;
}

#define CP_ASYNC16(dst, src) asm volatile("cp.async.cg.shared.global [%0], [%1], 16;" :: "r"(dst), "l"(src))
#define CP_ASYNC4(dst, src)  asm volatile("cp.async.ca.shared.global [%0], [%1], 4;" :: "r"(dst), "l"(src))
#define CP_COMMIT() asm volatile("cp.async.commit_group;" ::: "memory")
#define CP_WAIT0() asm volatile("cp.async.wait_group 0;" ::: "memory")

// ---------------- mma.sync helpers (bf16, m16n8k16) ----------------
__device__ __forceinline__ void ldm_x4(uint32_t* a, uint32_t addr) {
    asm volatile("ldmatrix.sync.aligned.m8n8.x4.shared.b16 {%0,%1,%2,%3}, [%4];"
                 : "=r"(a[0]), "=r"(a[1]), "=r"(a[2]), "=r"(a[3]) : "r"(addr));
}
__device__ __forceinline__ void ldm_x4t(uint32_t* a, uint32_t addr) {
    asm volatile("ldmatrix.sync.aligned.m8n8.x4.trans.shared.b16 {%0,%1,%2,%3}, [%4];"
                 : "=r"(a[0]), "=r"(a[1]), "=r"(a[2]), "=r"(a[3]) : "r"(addr));
}
__device__ __forceinline__ void ldm_x2(uint32_t* b, uint32_t addr) {
    asm volatile("ldmatrix.sync.aligned.m8n8.x2.shared.b16 {%0,%1}, [%2];"
                 : "=r"(b[0]), "=r"(b[1]) : "r"(addr));
}
__device__ __forceinline__ void mma16816(float* d, const uint32_t* a, const uint32_t* b) {
    asm volatile("mma.sync.aligned.m16n8k16.row.col.f32.bf16.bf16.f32 "
                 "{%0,%1,%2,%3}, {%4,%5,%6,%7}, {%8,%9}, {%0,%1,%2,%3};"
                 : "+f"(d[0]), "+f"(d[1]), "+f"(d[2]), "+f"(d[3])
                 : "r"(a[0]), "r"(a[1]), "r"(a[2]), "r"(a[3]), "r"(b[0]), "r"(b[1]));
}

// ---------------- 0. adj -> bitmask (streaming) ----------------
__global__ __launch_bounds__(256) void adjbits_kernel(const float* __restrict__ adj) {
    size_t t = (size_t)blockIdx.x * 256 + threadIdx.x;   // one byte (8 j's) per thread
    const float4* a4 = (const float4*)adj + t * 2;
    float4 v0 = a4[0], v1 = a4[1];
    unsigned b = (v0.x > 0.f) | ((v0.y > 0.f) << 1) | ((v0.z > 0.f) << 2) | ((v0.w > 0.f) << 3)
               | ((v1.x > 0.f) << 4) | ((v1.y > 0.f) << 5) | ((v1.z > 0.f) << 6) | ((v1.w > 0.f) << 7);
    ((unsigned char*)g_adjbits)[t] = (unsigned char)b;
}

// ---------------- 1. structure = relu(x @ fea_W + fea_b) ----------------
__global__ __launch_bounds__(256) void struct_kernel(const float* __restrict__ A,
                                                     const float* __restrict__ W,
                                                     const float* __restrict__ bias) {
    __shared__ float As[16][128];
    const int i0 = blockIdx.x * 16;
    const int tid = threadIdx.x;
    const int n = tid & 63, rg = tid >> 6;

    for (int idx = tid; idx < 16 * 128; idx += 256)
        As[idx >> 7][idx & 127] = A[(size_t)(i0 + (idx >> 7)) * 128 + (idx & 127)];
    __syncthreads();

    float acc[4] = {0.f, 0.f, 0.f, 0.f};
#pragma unroll 4
    for (int k = 0; k < 128; k++) {
        float b = W[(size_t)k * 64 + n];
#pragma unroll
        for (int r = 0; r < 4; r++) acc[r] += As[rg * 4 + r][k] * b;
    }
    float bv = bias[n];
#pragma unroll
    for (int r = 0; r < 4; r++)
        g_struct[(size_t)(i0 + rg * 4 + r) * 64 + n] = fmaxf(acc[r] + bv, 0.f);
}

// ---------------- 2. Wh = structure @ gat_W (bf16 hi/lo), fused s1/s2/max(s2) ----------------
__global__ __launch_bounds__(256) void wh_s1s2_kernel(const float* __restrict__ W,
                                                      const float* __restrict__ gat_a) {
    __shared__ float As[16][64];
    __shared__ float r1[8][8], r2[8][8];
    const int i0 = blockIdx.x * 16;
    const int tid = threadIdx.x;
    const int n = tid & 127, rg = tid >> 7;

    for (int idx = tid; idx < 16 * 64; idx += 256)
        As[idx >> 6][idx & 63] = g_struct[(size_t)(i0 + (idx >> 6)) * 64 + (idx & 63)];
    __syncthreads();

    float acc[8];
#pragma unroll
    for (int r = 0; r < 8; r++) acc[r] = 0.f;
#pragma unroll 4
    for (int k = 0; k < 64; k++) {
        float b = W[(size_t)k * 128 + n];
#pragma unroll
        for (int r = 0; r < 8; r++) acc[r] += As[rg * 8 + r][k] * b;
    }
#pragma unroll
    for (int r = 0; r < 8; r++) {
        float v = acc[r];
        __nv_bfloat16 hi = __float2bfloat16(v);
        __nv_bfloat16 lo = __float2bfloat16(v - __bfloat162float(hi));
        g_Whh[(size_t)(i0 + rg * 8 + r) * 128 + n] = hi;
        g_Whl[(size_t)(i0 + rg * 8 + r) * 128 + n] = lo;
    }

    float a1v = gat_a[n], a2v = gat_a[128 + n];
    int warp = tid >> 5, lane = tid & 31;
#pragma unroll
    for (int r = 0; r < 8; r++) {
        float v1 = acc[r] * a1v, v2 = acc[r] * a2v;
#pragma unroll
        for (int off = 16; off; off >>= 1) {
            v1 += __shfl_xor_sync(0xffffffffu, v1, off);
            v2 += __shfl_xor_sync(0xffffffffu, v2, off);
        }
        if (lane == 0) { r1[warp][r] = v1; r2[warp][r] = v2; }
    }
    __syncthreads();
    if (tid < 16) {
        int rgg = tid >> 3, rr = tid & 7;
        float s1 = r1[rgg * 4 + 0][rr] + r1[rgg * 4 + 1][rr] + r1[rgg * 4 + 2][rr] + r1[rgg * 4 + 3][rr];
        float s2 = r2[rgg * 4 + 0][rr] + r2[rgg * 4 + 1][rr] + r2[rgg * 4 + 2][rr] + r2[rgg * 4 + 3][rr];
        g_s1[i0 + tid] = s1;
        g_s2[i0 + tid] = s2;
        float m = s2;
#pragma unroll
        for (int off = 8; off; off >>= 1) m = fmaxf(m, __shfl_xor_sync(0x0000ffffu, m, off));
        if (tid == 0) atomicMax(&g_s2max_bits, float_key(m));
    }
}

// ---------------- 3. precompute A,B,C,D ----------------
__global__ void vec_kernel() {
    int i = blockIdx.x * 256 + threadIdx.x;
    float s2max = key_float(g_s2max_bits);
    float t = g_s1[i] + s2max;
    float m = t > 0.f ? t : 0.2f * t;
    g_A[i] = expf(t - m);
    g_C[i] = expf(0.2f * t - m);
    float u = g_s2[i] - s2max;
    g_B[i] = expf(u);
    g_D[i] = expf(0.2f * u);
}

// ---------------- 4. attention partial: bitmask + cp.async pipelined mma split-bf16 ----------------
#define PLD 40
#define WLD 136
#define WHH_OFF(b) ((b) * 8704)
#define WHL_OFF(b) (17408 + (b) * 8704)
#define PH_OFF 34816
#define PL_OFF 39936
#define S2BD_OFF(b) (45056 + (b) * 384)
#define BITS_OFF(b) (45824 + (b) * 256)
#define SAC_OFF 46336
#define ATTN_SMEM 47104

__global__ __launch_bounds__(256, 3) void attn_mma_kernel() {
    extern __shared__ __align__(16) char smem[];
    const uint32_t sb = smem_u32(smem);
    float* sac = (float*)(smem + SAC_OFF);   // s1[64], A[64], C[64]

    const int i0 = blockIdx.x * 64;
    const int jb = blockIdx.y * JSEG;
    const int tid = threadIdx.x;
    const int lane = tid & 31, wid = tid >> 5;
    const int wm = wid & 1, wn = wid >> 1;
    if (tid < 64) {
        sac[tid] = g_s1[i0 + tid];
        sac[64 + tid] = g_A[i0 + tid];
        sac[128 + tid] = g_C[i0 + tid];
    }

    const int c4 = (tid & 7) * 4;
    const int rp = tid >> 3;

    float d[2][4][4];
#pragma unroll
    for (int mt = 0; mt < 2; mt++)
#pragma unroll
        for (int nt = 0; nt < 4; nt++)
#pragma unroll
            for (int q = 0; q < 4; q++) d[mt][nt][q] = 0.f;
    float dsum[2] = {0.f, 0.f};

    const int whrow = tid >> 4, whch = tid & 15;

    auto issue_cp = [&](int t) {
        int b = t & 1;
        int jc = jb + t * 32;
#pragma unroll
        for (int e = 0; e < 2; e++) {
            int row = whrow + e * 16;
            CP_ASYNC16(sb + WHH_OFF(b) + row * 272 + whch * 16,
                       (const char*)g_Whh + ((size_t)(jc + row) * 128 + whch * 8) * 2);
            CP_ASYNC16(sb + WHL_OFF(b) + row * 272 + whch * 16,
                       (const char*)g_Whl + ((size_t)(jc + row) * 128 + whch * 8) * 2);
        }
        if (tid < 24) {
            int arr = tid >> 3, sub = tid & 7;
            const float* src = arr == 0 ? g_s2 : (arr == 1 ? g_B : g_D);
            CP_ASYNC4(sb + S2BD_OFF(b) + (arr * 32 + sub * 4) * 4, (const char*)(src + jc + sub * 4));
            CP_ASYNC4(sb + S2BD_OFF(b) + (arr * 32 + sub * 4 + 1) * 4, (const char*)(src + jc + sub * 4 + 1));
            CP_ASYNC4(sb + S2BD_OFF(b) + (arr * 32 + sub * 4 + 2) * 4, (const char*)(src + jc + sub * 4 + 2));
            CP_ASYNC4(sb + S2BD_OFF(b) + (arr * 32 + sub * 4 + 3) * 4, (const char*)(src + jc + sub * 4 + 3));
        }
        if (tid < 64) {
            CP_ASYNC4(sb + BITS_OFF(b) + tid * 4,
                      (const char*)(g_adjbits + (size_t)(i0 + tid) * 256 + (jc >> 5)));
        }
    };

    issue_cp(0);
    CP_COMMIT();

    const int T = JSEG / 32;
    for (int t = 0; t < T; t++) {
        const int b = t & 1;
        CP_WAIT0();
        __syncthreads();
        if (t + 1 < T) { issue_cp(t + 1); CP_COMMIT(); }

        // transform: bits + factor vectors -> p hi/lo bf16 tiles
        {
            const float* s2bd = (const float*)(smem + S2BD_OFF(b));
            float4 s2v = ((const float4*)s2bd)[tid & 7];
            float4 Bv = ((const float4*)(s2bd + 32))[tid & 7];
            float4 Dv = ((const float4*)(s2bd + 64))[tid & 7];
            const uint32_t* bits = (const uint32_t*)(smem + BITS_OFF(b));
#pragma unroll
            for (int rr = 0; rr < 2; rr++) {
                int r = rp * 2 + rr;
                uint32_t w = bits[r];
                float s1 = sac[r], Av = sac[64 + r], Cv = sac[128 + r];
                float pv[4];
                { float tt = s1 + s2v.x; pv[0] = (w >> (c4 + 0)) & 1 ? (tt > 0.f ? Av * Bv.x : Cv * Dv.x) : 0.f; }
                { float tt = s1 + s2v.y; pv[1] = (w >> (c4 + 1)) & 1 ? (tt > 0.f ? Av * Bv.y : Cv * Dv.y) : 0.f; }
                { float tt = s1 + s2v.z; pv[2] = (w >> (c4 + 2)) & 1 ? (tt > 0.f ? Av * Bv.z : Cv * Dv.z) : 0.f; }
                { float tt = s1 + s2v.w; pv[3] = (w >> (c4 + 3)) & 1 ? (tt > 0.f ? Av * Bv.w : Cv * Dv.w) : 0.f; }
                ushort4 h4, l4;
                unsigned short* hp = (unsigned short*)&h4;
                unsigned short* lp = (unsigned short*)&l4;
#pragma unroll
                for (int q = 0; q < 4; q++) {
                    __nv_bfloat16 hi = __float2bfloat16(pv[q]);
                    __nv_bfloat16 lo = __float2bfloat16(pv[q] - __bfloat162float(hi));
                    hp[q] = *(unsigned short*)&hi;
                    lp[q] = *(unsigned short*)&lo;
                }
                *(ushort4*)(smem + PH_OFF + (r * PLD + c4) * 2) = h4;
                *(ushort4*)(smem + PL_OFF + (r * PLD + c4) * 2) = l4;
                dsum[rr] += (pv[0] + pv[1]) + (pv[2] + pv[3]);
            }
        }
        __syncthreads();

        // mma: d += ph*Whh + pl*Whh + ph*Whl
        const uint32_t ph_b = sb + PH_OFF, pl_b = sb + PL_OFF;
        const uint32_t whh_b = sb + WHH_OFF(b), whl_b = sb + WHL_OFF(b);
#pragma unroll
        for (int ks = 0; ks < 2; ks++) {
            int k0 = ks * 16;
            uint32_t aph[2][4], apl[2][4], bhh[2][4], bhl[2][4];
#pragma unroll
            for (int mt = 0; mt < 2; mt++) {
                uint32_t off = ((wm * 32 + mt * 16 + (lane & 15)) * PLD + k0 + (lane >> 4) * 8) * 2;
                ldm_x4(aph[mt], ph_b + off);
                ldm_x4(apl[mt], pl_b + off);
            }
#pragma unroll
            for (int np = 0; np < 2; np++) {
                uint32_t off = ((k0 + (lane & 15)) * WLD + wn * 32 + np * 16 + (lane >> 4) * 8) * 2;
                ldm_x4t(bhh[np], whh_b + off);
                ldm_x4t(bhl[np], whl_b + off);
            }
#pragma unroll
            for (int mt = 0; mt < 2; mt++)
#pragma unroll
                for (int np = 0; np < 2; np++)
#pragma unroll
                    for (int h = 0; h < 2; h++) {
                        int nt = np * 2 + h;
                        mma16816(d[mt][nt], aph[mt], &bhh[np][h * 2]);
                        mma16816(d[mt][nt], apl[mt], &bhh[np][h * 2]);
                        mma16816(d[mt][nt], aph[mt], &bhl[np][h * 2]);
                    }
        }
    }

#pragma unroll
    for (int off = 4; off; off >>= 1) {
        dsum[0] += __shfl_down_sync(0xffffffffu, dsum[0], off, 8);
        dsum[1] += __shfl_down_sync(0xffffffffu, dsum[1], off, 8);
    }
    if ((tid & 7) == 0) {
        g_pden[(size_t)blockIdx.y * NROWS + i0 + rp * 2] = dsum[0];
        g_pden[(size_t)blockIdx.y * NROWS + i0 + rp * 2 + 1] = dsum[1];
    }

    float* pa = g_pacc + (size_t)blockIdx.y * NROWS * IN_DIM;
    const int g = lane >> 2, tig = lane & 3;
#pragma unroll
    for (int mt = 0; mt < 2; mt++) {
        int r0 = i0 + wm * 32 + mt * 16 + g;
#pragma unroll
        for (int nt = 0; nt < 4; nt++) {
            int col = wn * 32 + nt * 8 + tig * 2;
            *(float2*)&pa[(size_t)r0 * IN_DIM + col] = make_float2(d[mt][nt][0], d[mt][nt][1]);
            *(float2*)&pa[(size_t)(r0 + 8) * IN_DIM + col] = make_float2(d[mt][nt][2], d[mt][nt][3]);
        }
    }
}

// ---------------- 4b. combine: emb = elu(sum/den), split to bf16 hi+lo ----------------
__global__ __launch_bounds__(256) void combine_kernel() {
    int idx = blockIdx.x * 256 + threadIdx.x;
    int row = idx >> 5;
    float den = 0.f;
    float4 acc = make_float4(0.f, 0.f, 0.f, 0.f);
#pragma unroll
    for (int s = 0; s < NSPLIT; s++) {
        den += g_pden[(size_t)s * NROWS + row];
        float4 v = ((const float4*)g_pacc)[(size_t)s * NROWS * 32 + idx];
        acc.x += v.x; acc.y += v.y; acc.z += v.z; acc.w += v.w;
    }
    float inv = 1.0f / den;
    float o[4] = {acc.x * inv, acc.y * inv, acc.z * inv, acc.w * inv};
    __nv_bfloat16 hi[4], lo[4];
#pragma unroll
    for (int j = 0; j < 4; j++) {
        o[j] = o[j] > 0.f ? o[j] : expm1f(o[j]);
        hi[j] = __float2bfloat16(o[j]);
        lo[j] = __float2bfloat16(o[j] - __bfloat162float(hi[j]));
    }
    *(ull*)&g_embh[(size_t)idx * 4] = *(const ull*)hi;
    *(ull*)&g_embl[(size_t)idx * 4] = *(const ull*)lo;
}

// ---------------- 5. con_adj = emb @ emb.T: 4 resident tiles, 512 thr, triangular grid ----------------
#define LDB 136
#define TILE_BYTES2 (128 * LDB * 2)
#define SYRK_SMEM (4 * TILE_BYTES2)

__device__ __forceinline__ void syrk_pass(uint32_t x_b, uint32_t y_b, int m0, int n0,
                                          int lane, float d[2][4][4]) {
#pragma unroll
    for (int ks = 0; ks < 8; ks++) {
        int k0 = ks * 16;
        uint32_t afr[2][4], bfr[4][2];
#pragma unroll
        for (int mt = 0; mt < 2; mt++) {
            int row = m0 + mt * 16 + (lane & 15);
            int col = k0 + (lane >> 4) * 8;
            ldm_x4(afr[mt], x_b + (row * LDB + col) * 2);
        }
#pragma unroll
        for (int nt = 0; nt < 4; nt++) {
            int row = n0 + nt * 8 + (lane & 7);
            int col = k0 + ((lane >> 3) & 1) * 8;
            ldm_x2(bfr[nt], y_b + (row * LDB + col) * 2);
        }
#pragma unroll
        for (int mt = 0; mt < 2; mt++)
#pragma unroll
            for (int nt = 0; nt < 4; nt++)
                mma16816(d[mt][nt], afr[mt], bfr[nt]);
    }
}

__device__ __forceinline__ void syrk_store(float* out, int r_base, int c_base,
                                           int m0, int n0, int lane, float d[2][4][4]) {
    const int g = lane >> 2, tig = lane & 3;
#pragma unroll
    for (int mt = 0; mt < 2; mt++) {
        int r0 = r_base + m0 + mt * 16 + g;
#pragma unroll
        for (int nt = 0; nt < 4; nt++) {
            int c0 = c_base + n0 + nt * 8 + tig * 2;
            *(float2*)&out[(size_t)r0 * NROWS + c0] = make_float2(d[mt][nt][0], d[mt][nt][1]);
            *(float2*)&out[(size_t)(r0 + 8) * NROWS + c0] = make_float2(d[mt][nt][2], d[mt][nt][3]);
        }
    }
}

__global__ __launch_bounds__(512) void syrk_mma_kernel(float* __restrict__ out) {
    // triangular decode: blockIdx.x -> (bi, bj), bj >= bi
    int t = blockIdx.x, bi = 0, rem = 64;
    while (t >= rem) { t -= rem; rem--; bi++; }
    const int bj = bi + t;

    extern __shared__ __align__(16) char smem[];
    char* Ah = smem;
    char* Al = smem + TILE_BYTES2;
    char* Bh = smem + 2 * TILE_BYTES2;
    char* Bl = smem + 3 * TILE_BYTES2;
    const uint32_t ah_b = smem_u32(Ah), al_b = smem_u32(Al);
    const uint32_t bh_b = smem_u32(Bh), bl_b = smem_u32(Bl);

    const int tid = threadIdx.x;
    const int lane = tid & 31, wid = tid >> 5;
    const int i0 = bi * 128, j0 = bj * 128;
    const int m0 = (wid & 3) * 32, n0 = (wid >> 2) * 32;

    // load all 4 tiles once (cp.async)
#pragma unroll
    for (int e = 0; e < 4; e++) {
        int idx = tid + e * 512;
        int row = idx >> 4, ch = idx & 15;
        CP_ASYNC16(ah_b + row * 272 + ch * 16, (const char*)g_embh + ((size_t)(i0 + row) * 128 + ch * 8) * 2);
        CP_ASYNC16(al_b + row * 272 + ch * 16, (const char*)g_embl + ((size_t)(i0 + row) * 128 + ch * 8) * 2);
        CP_ASYNC16(bh_b + row * 272 + ch * 16, (const char*)g_embh + ((size_t)(j0 + row) * 128 + ch * 8) * 2);
        CP_ASYNC16(bl_b + row * 272 + ch * 16, (const char*)g_embl + ((size_t)(j0 + row) * 128 + ch * 8) * 2);
    }
    CP_COMMIT();
    CP_WAIT0();
    __syncthreads();

    float d[2][4][4];
#pragma unroll
    for (int mt = 0; mt < 2; mt++)
#pragma unroll
        for (int nt = 0; nt < 4; nt++)
#pragma unroll
            for (int q = 0; q < 4; q++) d[mt][nt][q] = 0.f;

    syrk_pass(ah_b, bh_b, m0, n0, lane, d);
    syrk_pass(ah_b, bl_b, m0, n0, lane, d);
    syrk_pass(al_b, bh_b, m0, n0, lane, d);
    syrk_store(out, i0, j0, m0, n0, lane, d);

    if (bi != bj) {
#pragma unroll
        for (int mt = 0; mt < 2; mt++)
#pragma unroll
            for (int nt = 0; nt < 4; nt++)
#pragma unroll
                for (int q = 0; q < 4; q++) d[mt][nt][q] = 0.f;
        syrk_pass(bh_b, ah_b, m0, n0, lane, d);
        syrk_pass(bh_b, al_b, m0, n0, lane, d);
        syrk_pass(bl_b, ah_b, m0, n0, lane, d);
        syrk_store(out, j0, i0, m0, n0, lane, d);
    }
}

// ---------------- 6. encoder: gates = x @ enc_W_ih.T, LSTM fused ----------------
__global__ __launch_bounds__(256) void enc_fused(const float* __restrict__ x,
                                                 const float* __restrict__ W,
                                                 const float* __restrict__ b_ih,
                                                 const float* __restrict__ b_hh) {
    __shared__ float As[16][128];
    __shared__ float Ws[16][257];
    __shared__ float gsm[16][256];
    const int i0 = blockIdx.x * 16;
    const int tid = threadIdx.x;
    const int n = tid;

    for (int idx = tid; idx < 16 * 128; idx += 256)
        As[idx >> 7][idx & 127] = x[(size_t)(i0 + (idx >> 7)) * 128 + (idx & 127)];

    float acc[16];
#pragma unroll
    for (int r = 0; r < 16; r++) acc[r] = 0.f;

    for (int kt = 0; kt < 128; kt += 16) {
        __syncthreads();
        for (int f = tid; f < 16 * 256; f += 256) {
            int n2 = f >> 4, kk = f & 15;
            Ws[kk][n2] = W[(size_t)n2 * 128 + kt + kk];
        }
        __syncthreads();
#pragma unroll
        for (int kk = 0; kk < 16; kk++) {
            float b = Ws[kk][n];
#pragma unroll
            for (int r = 0; r < 16; r++) acc[r] += As[r][kt + kk] * b;
        }
    }
    __syncthreads();
#pragma unroll
    for (int r = 0; r < 16; r++) gsm[r][n] = acc[r];
    __syncthreads();

#pragma unroll
    for (int e = 0; e < 4; e++) {
        int idx = tid + e * 256;
        int row = idx >> 6, hh = idx & 63;
        float gi = gsm[row][hh] + b_ih[hh] + b_hh[hh];
        float gg = gsm[row][128 + hh] + b_ih[128 + hh] + b_hh[128 + hh];
        float go = gsm[row][192 + hh] + b_ih[192 + hh] + b_hh[192 + hh];
        float c = sigmoidf_(gi) * tanhf(gg);
        g_henc[(size_t)(i0 + row) * 64 + hh] = sigmoidf_(go) * tanhf(c);
    }
}

// ---------------- 7. decoder: gates = h_enc @ dec_W_ih.T, LSTM fused ----------------
__global__ __launch_bounds__(512) void dec_fused(const float* __restrict__ W,
                                                 const float* __restrict__ b_ih,
                                                 const float* __restrict__ b_hh,
                                                 float* __restrict__ out) {
    __shared__ union {
        struct { float As[16][64]; float Ws[16][513]; } in;
        float gsm[16][512];
    } sm;
    const int i0 = blockIdx.x * 16;
    const int tid = threadIdx.x;
    const int n = tid;

    for (int idx = tid; idx < 16 * 64; idx += 512)
        sm.in.As[idx >> 6][idx & 63] = g_henc[(size_t)(i0 + (idx >> 6)) * 64 + (idx & 63)];

    float acc[16];
#pragma unroll
    for (int r = 0; r < 16; r++) acc[r] = 0.f;

    for (int kt = 0; kt < 64; kt += 16) {
        __syncthreads();
        for (int f = tid; f < 16 * 512; f += 512) {
            int n2 = f >> 4, kk = f & 15;
            sm.in.Ws[kk][n2] = W[(size_t)n2 * 64 + kt + kk];
        }
        __syncthreads();
#pragma unroll
        for (int kk = 0; kk < 16; kk++) {
            float b = sm.in.Ws[kk][n];
#pragma unroll
            for (int r = 0; r < 16; r++) acc[r] += sm.in.As[r][kt + kk] * b;
        }
    }
    __syncthreads();
#pragma unroll
    for (int r = 0; r < 16; r++) sm.gsm[r][n] = acc[r];
    __syncthreads();

#pragma unroll
    for (int e = 0; e < 4; e++) {
        int idx = tid + e * 512;
        int row = idx >> 7, hh = idx & 127;
        float gi = sm.gsm[row][hh] + b_ih[hh] + b_hh[hh];
        float gg = sm.gsm[row][256 + hh] + b_ih[256 + hh] + b_hh[256 + hh];
        float go = sm.gsm[row][384 + hh] + b_ih[384 + hh] + b_hh[384 + hh];
        float c = sigmoidf_(gi) * tanhf(gg);
        out[(size_t)(i0 + row) * 128 + hh] = sigmoidf_(go) * tanhf(c);
    }
}

// ---------------- launch ----------------
extern "C" void kernel_launch(void* const* d_in, const int* in_sizes, int n_in,
                              void* d_out, int out_size) {
    const float* x = (const float*)d_in[0];
    const float* adj = (const float*)d_in[1];
    const float* fea_W = (const float*)d_in[2];
    const float* fea_b = (const float*)d_in[3];
    const float* gat_W = (const float*)d_in[4];
    const float* gat_a = (const float*)d_in[5];
    const float* enc_W_ih = (const float*)d_in[6];
    const float* enc_b_ih = (const float*)d_in[8];
    const float* enc_b_hh = (const float*)d_in[9];
    const float* dec_W_ih = (const float*)d_in[10];
    const float* dec_b_ih = (const float*)d_in[12];
    const float* dec_b_hh = (const float*)d_in[13];

    float* out = (float*)d_out;
    float* con_adj = out;
    float* att_adj = out + (size_t)NROWS * NROWS;

    cudaFuncSetAttribute(attn_mma_kernel, cudaFuncAttributeMaxDynamicSharedMemorySize, ATTN_SMEM);
    cudaFuncSetAttribute(syrk_mma_kernel, cudaFuncAttributeMaxDynamicSharedMemorySize, SYRK_SMEM);

    adjbits_kernel<<<NROWS * NROWS / 8 / 256, 256>>>(adj);                  // 0
    struct_kernel<<<NROWS / 16, 256>>>(x, fea_W, fea_b);                    // 1
    wh_s1s2_kernel<<<NROWS / 16, 256>>>(gat_W, gat_a);                      // 2
    vec_kernel<<<NROWS / 256, 256>>>();                                     // 3
    attn_mma_kernel<<<dim3(NROWS / 64, NSPLIT), 256, ATTN_SMEM>>>();        // 4
    combine_kernel<<<NROWS * 32 / 256, 256>>>();                            // 5
    syrk_mma_kernel<<<2080, 512, SYRK_SMEM>>>(con_adj);                     // 6
    enc_fused<<<NROWS / 16, 256>>>(x, enc_W_ih, enc_b_ih, enc_b_hh);        // 7
    dec_fused<<<NROWS / 16, 512>>>(dec_W_ih, dec_b_ih, dec_b_hh, att_adj);  // 8
}

// round 12
// speedup vs baseline: 1.0546x; 1.0546x over previous
#include <cuda_runtime.h>
#include <cuda_bf16.h>
#include <cstdint>

#define NROWS 8192
#define IN_DIM 128
#define HID 64
#define NSPLIT 16
#define JSEG (NROWS / NSPLIT)

typedef unsigned long long ull;

// ---------------- scratch (static device globals; no allocation) ----------------
__device__ __align__(16) float g_struct[NROWS * HID];
__device__ __align__(16) __nv_bfloat16 g_Whh[NROWS * IN_DIM];
__device__ __align__(16) __nv_bfloat16 g_Whl[NROWS * IN_DIM];
__device__ __align__(16) float g_s1[NROWS];
__device__ __align__(16) float g_s2[NROWS];
__device__ __align__(16) float g_A[NROWS];
__device__ __align__(16) float g_B[NROWS];
__device__ __align__(16) float g_C[NROWS];
__device__ __align__(16) float g_D[NROWS];
__device__ unsigned g_s2max_bits = 0u;
__device__ __align__(16) float g_henc[NROWS * HID];
__device__ __align__(16) __nv_bfloat16 g_embh[NROWS * IN_DIM];
__device__ __align__(16) __nv_bfloat16 g_embl[NROWS * IN_DIM];
__device__ __align__(16) float g_pacc[NSPLIT * NROWS * IN_DIM];
__device__ __align__(16) float g_pden[NSPLIT * NROWS];

// ---------------- helpers ----------------
__device__ __forceinline__ float sigmoidf_(float x) { return 1.0f / (1.0f + __expf(-x)); }

__device__ __forceinline__ unsigned float_key(float f) {
    unsigned b = __float_as_uint(f);
    return (b & 0x80000000u) ? ~b : (b | 0x80000000u);
}
__device__ __forceinline__ float key_float(unsigned k) {
    unsigned b = (k & 0x80000000u) ? (k & 0x7fffffffu) : ~k;
    return __uint_as_float(b);
}
__device__ __forceinline__ uint32_t smem_u32(const void* p) {
    uint32_t a;
    asm("{ .reg .u64 t; cvta.to.shared.u64 t, %1; cvt.u32.u64 %0, t; }" : "=r"(a) : "l"(p));
    return a;
}

#define CP_ASYNC16(dst, src) asm volatile("cp.async.cg.shared.global [%0], [%1], 16;" :: "r"(dst), "l"(src))
#define CP_COMMIT() asm volatile("cp.async.commit_group;" ::: "memory")
#define CP_WAIT0() asm volatile("cp.async.wait_group 0;" ::: "memory")

// ---------------- mma.sync helpers (bf16, m16n8k16) ----------------
__device__ __forceinline__ void ldm_x4(uint32_t* a, uint32_t addr) {
    asm volatile("ldmatrix.sync.aligned.m8n8.x4.shared.b16 {%0,%1,%2,%3}, [%4];"
                 : "=r"(a[0]), "=r"(a[1]), "=r"(a[2]), "=r"(a[3]) : "r"(addr));
}
__device__ __forceinline__ void ldm_x4t(uint32_t* a, uint32_t addr) {
    asm volatile("ldmatrix.sync.aligned.m8n8.x4.trans.shared.b16 {%0,%1,%2,%3}, [%4];"
                 : "=r"(a[0]), "=r"(a[1]), "=r"(a[2]), "=r"(a[3]) : "r"(addr));
}
__device__ __forceinline__ void ldm_x2(uint32_t* b, uint32_t addr) {
    asm volatile("ldmatrix.sync.aligned.m8n8.x2.shared.b16 {%0,%1}, [%2];"
                 : "=r"(b[0]), "=r"(b[1]) : "r"(addr));
}
__device__ __forceinline__ void mma16816(float* d, const uint32_t* a, const uint32_t* b) {
    asm volatile("mma.sync.aligned.m16n8k16.row.col.f32.bf16.bf16.f32 "
                 "{%0,%1,%2,%3}, {%4,%5,%6,%7}, {%8,%9}, {%0,%1,%2,%3};"
                 : "+f"(d[0]), "+f"(d[1]), "+f"(d[2]), "+f"(d[3])
                 : "r"(a[0]), "r"(a[1]), "r"(a[2]), "r"(a[3]), "r"(b[0]), "r"(b[1]));
}

// ---------------- 1. structure = relu(x @ fea_W + fea_b) ----------------
__global__ __launch_bounds__(256) void struct_kernel(const float* __restrict__ A,
                                                     const float* __restrict__ W,
                                                     const float* __restrict__ bias) {
    __shared__ float As[16][128];
    const int i0 = blockIdx.x * 16;
    const int tid = threadIdx.x;
    const int n = tid & 63, rg = tid >> 6;

    for (int idx = tid; idx < 16 * 128; idx += 256)
        As[idx >> 7][idx & 127] = A[(size_t)(i0 + (idx >> 7)) * 128 + (idx & 127)];
    __syncthreads();

    float acc[4] = {0.f, 0.f, 0.f, 0.f};
#pragma unroll 4
    for (int k = 0; k < 128; k++) {
        float b = W[(size_t)k * 64 + n];
#pragma unroll
        for (int r = 0; r < 4; r++) acc[r] += As[rg * 4 + r][k] * b;
    }
    float bv = bias[n];
#pragma unroll
    for (int r = 0; r < 4; r++)
        g_struct[(size_t)(i0 + rg * 4 + r) * 64 + n] = fmaxf(acc[r] + bv, 0.f);
}

// ---------------- 2. Wh = structure @ gat_W (bf16 hi/lo), fused s1/s2/max(s2) ----------------
__global__ __launch_bounds__(256) void wh_s1s2_kernel(const float* __restrict__ W,
                                                      const float* __restrict__ gat_a) {
    __shared__ float As[16][64];
    __shared__ float r1[8][8], r2[8][8];
    const int i0 = blockIdx.x * 16;
    const int tid = threadIdx.x;
    const int n = tid & 127, rg = tid >> 7;

    for (int idx = tid; idx < 16 * 64; idx += 256)
        As[idx >> 6][idx & 63] = g_struct[(size_t)(i0 + (idx >> 6)) * 64 + (idx & 63)];
    __syncthreads();

    float acc[8];
#pragma unroll
    for (int r = 0; r < 8; r++) acc[r] = 0.f;
#pragma unroll 4
    for (int k = 0; k < 64; k++) {
        float b = W[(size_t)k * 128 + n];
#pragma unroll
        for (int r = 0; r < 8; r++) acc[r] += As[rg * 8 + r][k] * b;
    }
#pragma unroll
    for (int r = 0; r < 8; r++) {
        float v = acc[r];
        __nv_bfloat16 hi = __float2bfloat16(v);
        __nv_bfloat16 lo = __float2bfloat16(v - __bfloat162float(hi));
        g_Whh[(size_t)(i0 + rg * 8 + r) * 128 + n] = hi;
        g_Whl[(size_t)(i0 + rg * 8 + r) * 128 + n] = lo;
    }

    float a1v = gat_a[n], a2v = gat_a[128 + n];
    int warp = tid >> 5, lane = tid & 31;
#pragma unroll
    for (int r = 0; r < 8; r++) {
        float v1 = acc[r] * a1v, v2 = acc[r] * a2v;
#pragma unroll
        for (int off = 16; off; off >>= 1) {
            v1 += __shfl_xor_sync(0xffffffffu, v1, off);
            v2 += __shfl_xor_sync(0xffffffffu, v2, off);
        }
        if (lane == 0) { r1[warp][r] = v1; r2[warp][r] = v2; }
    }
    __syncthreads();
    if (tid < 16) {
        int rgg = tid >> 3, rr = tid & 7;
        float s1 = r1[rgg * 4 + 0][rr] + r1[rgg * 4 + 1][rr] + r1[rgg * 4 + 2][rr] + r1[rgg * 4 + 3][rr];
        float s2 = r2[rgg * 4 + 0][rr] + r2[rgg * 4 + 1][rr] + r2[rgg * 4 + 2][rr] + r2[rgg * 4 + 3][rr];
        g_s1[i0 + tid] = s1;
        g_s2[i0 + tid] = s2;
        float m = s2;
#pragma unroll
        for (int off = 8; off; off >>= 1) m = fmaxf(m, __shfl_xor_sync(0x0000ffffu, m, off));
        if (tid == 0) atomicMax(&g_s2max_bits, float_key(m));
    }
}

// ---------------- 3. precompute A,B,C,D ----------------
__global__ void vec_kernel() {
    int i = blockIdx.x * 256 + threadIdx.x;
    float s2max = key_float(g_s2max_bits);
    float t = g_s1[i] + s2max;
    float m = t > 0.f ? t : 0.2f * t;
    g_A[i] = expf(t - m);
    g_C[i] = expf(0.2f * t - m);
    float u = g_s2[i] - s2max;
    g_B[i] = expf(u);
    g_D[i] = expf(0.2f * u);
}

// ---------------- 4. attention partial: cp.async pipelined mma split-bf16 (R10 best) ----------------
#define PLD 40
#define WLD 136
#define WHH_OFF(b) ((b) * 8704)
#define WHL_OFF(b) (17408 + (b) * 8704)
#define ADJ_OFF(b) (34816 + (b) * 9216)
#define PH_OFF 53248
#define PL_OFF 58368
#define S2BD_OFF(b) (63488 + (b) * 384)
#define SAC_OFF 64256
#define ATTN_SMEM 65024

__global__ __launch_bounds__(256) void attn_mma_kernel(const float* __restrict__ adj) {
    extern __shared__ __align__(16) char smem[];
    const uint32_t sb = smem_u32(smem);
    float* sac = (float*)(smem + SAC_OFF);   // s1[64], A[64], C[64]

    const int i0 = blockIdx.x * 64;
    const int jb = blockIdx.y * JSEG;
    const int tid = threadIdx.x;
    const int lane = tid & 31, wid = tid >> 5;
    const int wm = wid & 1, wn = wid >> 1;
    if (tid < 64) {
        sac[tid] = g_s1[i0 + tid];
        sac[64 + tid] = g_A[i0 + tid];
        sac[128 + tid] = g_C[i0 + tid];
    }

    const int c4 = (tid & 7) * 4;
    const int rp = tid >> 3;

    float d[2][4][4];
#pragma unroll
    for (int mt = 0; mt < 2; mt++)
#pragma unroll
        for (int nt = 0; nt < 4; nt++)
#pragma unroll
            for (int q = 0; q < 4; q++) d[mt][nt][q] = 0.f;
    float dsum[2] = {0.f, 0.f};

    const int whrow = tid >> 4, whch = tid & 15;
    const int adrow = tid >> 3, adch = tid & 7;

    auto issue_cp = [&](int t) {
        int b = t & 1;
        int jc = jb + t * 32;
#pragma unroll
        for (int e = 0; e < 2; e++) {
            int row = whrow + e * 16;
            CP_ASYNC16(sb + WHH_OFF(b) + row * 272 + whch * 16,
                       (const char*)g_Whh + ((size_t)(jc + row) * 128 + whch * 8) * 2);
            CP_ASYNC16(sb + WHL_OFF(b) + row * 272 + whch * 16,
                       (const char*)g_Whl + ((size_t)(jc + row) * 128 + whch * 8) * 2);
            int arow = adrow + e * 32;
            CP_ASYNC16(sb + ADJ_OFF(b) + arow * 144 + adch * 16,
                       (const char*)adj + ((size_t)(i0 + arow) * NROWS + jc + adch * 4) * 4);
        }
        if (tid < 24) {
            int arr = tid >> 3, sub = tid & 7;
            const float* src = arr == 0 ? g_s2 : (arr == 1 ? g_B : g_D);
            CP_ASYNC16(sb + S2BD_OFF(b) + arr * 128 + sub * 16,
                       (const char*)(src + jc + sub * 4));
        }
    };

    issue_cp(0);
    CP_COMMIT();

    const int T = JSEG / 32;
    for (int t = 0; t < T; t++) {
        const int b = t & 1;
        CP_WAIT0();
        __syncthreads();
        if (t + 1 < T) { issue_cp(t + 1); CP_COMMIT(); }

        // transform: adj smem -> p hi/lo bf16 tiles
        {
            const float* s2bd = (const float*)(smem + S2BD_OFF(b));
            float4 s2v = ((const float4*)s2bd)[tid & 7];
            float4 Bv = ((const float4*)(s2bd + 32))[tid & 7];
            float4 Dv = ((const float4*)(s2bd + 64))[tid & 7];
            const float* adjs = (const float*)(smem + ADJ_OFF(b));
#pragma unroll
            for (int rr = 0; rr < 2; rr++) {
                int r = rp * 2 + rr;
                float4 av = *(const float4*)&adjs[r * 36 + c4];
                float s1 = sac[r], Av = sac[64 + r], Cv = sac[128 + r];
                float pv[4];
                { float tt = s1 + s2v.x; pv[0] = (av.x > 0.f) ? (tt > 0.f ? Av * Bv.x : Cv * Dv.x) : 0.f; }
                { float tt = s1 + s2v.y; pv[1] = (av.y > 0.f) ? (tt > 0.f ? Av * Bv.y : Cv * Dv.y) : 0.f; }
                { float tt = s1 + s2v.z; pv[2] = (av.z > 0.f) ? (tt > 0.f ? Av * Bv.z : Cv * Dv.z) : 0.f; }
                { float tt = s1 + s2v.w; pv[3] = (av.w > 0.f) ? (tt > 0.f ? Av * Bv.w : Cv * Dv.w) : 0.f; }
                ushort4 h4, l4;
                unsigned short* hp = (unsigned short*)&h4;
                unsigned short* lp = (unsigned short*)&l4;
#pragma unroll
                for (int q = 0; q < 4; q++) {
                    __nv_bfloat16 hi = __float2bfloat16(pv[q]);
                    __nv_bfloat16 lo = __float2bfloat16(pv[q] - __bfloat162float(hi));
                    hp[q] = *(unsigned short*)&hi;
                    lp[q] = *(unsigned short*)&lo;
                }
                *(ushort4*)(smem + PH_OFF + (r * PLD + c4) * 2) = h4;
                *(ushort4*)(smem + PL_OFF + (r * PLD + c4) * 2) = l4;
                dsum[rr] += (pv[0] + pv[1]) + (pv[2] + pv[3]);
            }
        }
        __syncthreads();

        // mma: d += ph*Whh + pl*Whh + ph*Whl
        const uint32_t ph_b = sb + PH_OFF, pl_b = sb + PL_OFF;
        const uint32_t whh_b = sb + WHH_OFF(b), whl_b = sb + WHL_OFF(b);
#pragma unroll
        for (int ks = 0; ks < 2; ks++) {
            int k0 = ks * 16;
            uint32_t aph[2][4], apl[2][4], bhh[2][4], bhl[2][4];
#pragma unroll
            for (int mt = 0; mt < 2; mt++) {
                uint32_t off = ((wm * 32 + mt * 16 + (lane & 15)) * PLD + k0 + (lane >> 4) * 8) * 2;
                ldm_x4(aph[mt], ph_b + off);
                ldm_x4(apl[mt], pl_b + off);
            }
#pragma unroll
            for (int np = 0; np < 2; np++) {
                uint32_t off = ((k0 + (lane & 15)) * WLD + wn * 32 + np * 16 + (lane >> 4) * 8) * 2;
                ldm_x4t(bhh[np], whh_b + off);
                ldm_x4t(bhl[np], whl_b + off);
            }
#pragma unroll
            for (int mt = 0; mt < 2; mt++)
#pragma unroll
                for (int np = 0; np < 2; np++)
#pragma unroll
                    for (int h = 0; h < 2; h++) {
                        int nt = np * 2 + h;
                        mma16816(d[mt][nt], aph[mt], &bhh[np][h * 2]);
                        mma16816(d[mt][nt], apl[mt], &bhh[np][h * 2]);
                        mma16816(d[mt][nt], aph[mt], &bhl[np][h * 2]);
                    }
        }
    }

#pragma unroll
    for (int off = 4; off; off >>= 1) {
        dsum[0] += __shfl_down_sync(0xffffffffu, dsum[0], off, 8);
        dsum[1] += __shfl_down_sync(0xffffffffu, dsum[1], off, 8);
    }
    if ((tid & 7) == 0) {
        g_pden[(size_t)blockIdx.y * NROWS + i0 + rp * 2] = dsum[0];
        g_pden[(size_t)blockIdx.y * NROWS + i0 + rp * 2 + 1] = dsum[1];
    }

    float* pa = g_pacc + (size_t)blockIdx.y * NROWS * IN_DIM;
    const int g = lane >> 2, tig = lane & 3;
#pragma unroll
    for (int mt = 0; mt < 2; mt++) {
        int r0 = i0 + wm * 32 + mt * 16 + g;
#pragma unroll
        for (int nt = 0; nt < 4; nt++) {
            int col = wn * 32 + nt * 8 + tig * 2;
            *(float2*)&pa[(size_t)r0 * IN_DIM + col] = make_float2(d[mt][nt][0], d[mt][nt][1]);
            *(float2*)&pa[(size_t)(r0 + 8) * IN_DIM + col] = make_float2(d[mt][nt][2], d[mt][nt][3]);
        }
    }
}

// ---------------- 4b. combine: emb = elu(sum/den), split to bf16 hi+lo ----------------
__global__ __launch_bounds__(256) void combine_kernel() {
    int idx = blockIdx.x * 256 + threadIdx.x;
    int row = idx >> 5;
    float den = 0.f;
    float4 acc = make_float4(0.f, 0.f, 0.f, 0.f);
#pragma unroll
    for (int s = 0; s < NSPLIT; s++) {
        den += g_pden[(size_t)s * NROWS + row];
        float4 v = ((const float4*)g_pacc)[(size_t)s * NROWS * 32 + idx];
        acc.x += v.x; acc.y += v.y; acc.z += v.z; acc.w += v.w;
    }
    float inv = 1.0f / den;
    float o[4] = {acc.x * inv, acc.y * inv, acc.z * inv, acc.w * inv};
    __nv_bfloat16 hi[4], lo[4];
#pragma unroll
    for (int j = 0; j < 4; j++) {
        o[j] = o[j] > 0.f ? o[j] : expm1f(o[j]);
        hi[j] = __float2bfloat16(o[j]);
        lo[j] = __float2bfloat16(o[j] - __bfloat162float(hi[j]));
    }
    *(ull*)&g_embh[(size_t)idx * 4] = *(const ull*)hi;
    *(ull*)&g_embl[(size_t)idx * 4] = *(const ull*)lo;
}

// ---------------- 5. con_adj = emb @ emb.T: 4 resident tiles, 512 thr, triangular grid ----------------
#define LDB 136
#define TILE_BYTES2 (128 * LDB * 2)
#define SYRK_SMEM (4 * TILE_BYTES2)

__device__ __forceinline__ void syrk_pass(uint32_t x_b, uint32_t y_b, int m0, int n0,
                                          int lane, float d[2][4][4]) {
#pragma unroll
    for (int ks = 0; ks < 8; ks++) {
        int k0 = ks * 16;
        uint32_t afr[2][4], bfr[4][2];
#pragma unroll
        for (int mt = 0; mt < 2; mt++) {
            int row = m0 + mt * 16 + (lane & 15);
            int col = k0 + (lane >> 4) * 8;
            ldm_x4(afr[mt], x_b + (row * LDB + col) * 2);
        }
#pragma unroll
        for (int nt = 0; nt < 4; nt++) {
            int row = n0 + nt * 8 + (lane & 7);
            int col = k0 + ((lane >> 3) & 1) * 8;
            ldm_x2(bfr[nt], y_b + (row * LDB + col) * 2);
        }
#pragma unroll
        for (int mt = 0; mt < 2; mt++)
#pragma unroll
            for (int nt = 0; nt < 4; nt++)
                mma16816(d[mt][nt], afr[mt], bfr[nt]);
    }
}

__device__ __forceinline__ void syrk_store(float* out, int r_base, int c_base,
                                           int m0, int n0, int lane, float d[2][4][4]) {
    const int g = lane >> 2, tig = lane & 3;
#pragma unroll
    for (int mt = 0; mt < 2; mt++) {
        int r0 = r_base + m0 + mt * 16 + g;
#pragma unroll
        for (int nt = 0; nt < 4; nt++) {
            int c0 = c_base + n0 + nt * 8 + tig * 2;
            *(float2*)&out[(size_t)r0 * NROWS + c0] = make_float2(d[mt][nt][0], d[mt][nt][1]);
            *(float2*)&out[(size_t)(r0 + 8) * NROWS + c0] = make_float2(d[mt][nt][2], d[mt][nt][3]);
        }
    }
}

__global__ __launch_bounds__(512) void syrk_mma_kernel(float* __restrict__ out) {
    // triangular decode: blockIdx.x -> (bi, bj), bj >= bi
    int t = blockIdx.x, bi = 0, rem = 64;
    while (t >= rem) { t -= rem; rem--; bi++; }
    const int bj = bi + t;

    extern __shared__ __align__(16) char smem[];
    const uint32_t ah_b = smem_u32(smem);
    const uint32_t al_b = ah_b + TILE_BYTES2;
    const uint32_t bh_b = ah_b + 2 * TILE_BYTES2;
    const uint32_t bl_b = ah_b + 3 * TILE_BYTES2;

    const int tid = threadIdx.x;
    const int lane = tid & 31, wid = tid >> 5;
    const int i0 = bi * 128, j0 = bj * 128;
    const int m0 = (wid & 3) * 32, n0 = (wid >> 2) * 32;

#pragma unroll
    for (int e = 0; e < 4; e++) {
        int idx = tid + e * 512;
        int row = idx >> 4, ch = idx & 15;
        CP_ASYNC16(ah_b + row * 272 + ch * 16, (const char*)g_embh + ((size_t)(i0 + row) * 128 + ch * 8) * 2);
        CP_ASYNC16(al_b + row * 272 + ch * 16, (const char*)g_embl + ((size_t)(i0 + row) * 128 + ch * 8) * 2);
        CP_ASYNC16(bh_b + row * 272 + ch * 16, (const char*)g_embh + ((size_t)(j0 + row) * 128 + ch * 8) * 2);
        CP_ASYNC16(bl_b + row * 272 + ch * 16, (const char*)g_embl + ((size_t)(j0 + row) * 128 + ch * 8) * 2);
    }
    CP_COMMIT();
    CP_WAIT0();
    __syncthreads();

    float d[2][4][4];
#pragma unroll
    for (int mt = 0; mt < 2; mt++)
#pragma unroll
        for (int nt = 0; nt < 4; nt++)
#pragma unroll
            for (int q = 0; q < 4; q++) d[mt][nt][q] = 0.f;

    syrk_pass(ah_b, bh_b, m0, n0, lane, d);
    syrk_pass(ah_b, bl_b, m0, n0, lane, d);
    syrk_pass(al_b, bh_b, m0, n0, lane, d);
    syrk_store(out, i0, j0, m0, n0, lane, d);

    if (bi != bj) {
#pragma unroll
        for (int mt = 0; mt < 2; mt++)
#pragma unroll
            for (int nt = 0; nt < 4; nt++)
#pragma unroll
                for (int q = 0; q < 4; q++) d[mt][nt][q] = 0.f;
        syrk_pass(bh_b, ah_b, m0, n0, lane, d);
        syrk_pass(bh_b, al_b, m0, n0, lane, d);
        syrk_pass(bl_b, ah_b, m0, n0, lane, d);
        syrk_store(out, j0, i0, m0, n0, lane, d);
    }
}

// ---------------- 6. encoder: gates = x @ enc_W_ih.T, LSTM fused ----------------
__global__ __launch_bounds__(256) void enc_fused(const float* __restrict__ x,
                                                 const float* __restrict__ W,
                                                 const float* __restrict__ b_ih,
                                                 const float* __restrict__ b_hh) {
    __shared__ float As[16][128];
    __shared__ float Ws[16][257];
    __shared__ float gsm[16][256];
    const int i0 = blockIdx.x * 16;
    const int tid = threadIdx.x;
    const int n = tid;

    for (int idx = tid; idx < 16 * 128; idx += 256)
        As[idx >> 7][idx & 127] = x[(size_t)(i0 + (idx >> 7)) * 128 + (idx & 127)];

    float acc[16];
#pragma unroll
    for (int r = 0; r < 16; r++) acc[r] = 0.f;

    for (int kt = 0; kt < 128; kt += 16) {
        __syncthreads();
        for (int f = tid; f < 16 * 256; f += 256) {
            int n2 = f >> 4, kk = f & 15;
            Ws[kk][n2] = W[(size_t)n2 * 128 + kt + kk];
        }
        __syncthreads();
#pragma unroll
        for (int kk = 0; kk < 16; kk++) {
            float b = Ws[kk][n];
#pragma unroll
            for (int r = 0; r < 16; r++) acc[r] += As[r][kt + kk] * b;
        }
    }
    __syncthreads();
#pragma unroll
    for (int r = 0; r < 16; r++) gsm[r][n] = acc[r];
    __syncthreads();

#pragma unroll
    for (int e = 0; e < 4; e++) {
        int idx = tid + e * 256;
        int row = idx >> 6, hh = idx & 63;
        float gi = gsm[row][hh] + b_ih[hh] + b_hh[hh];
        float gg = gsm[row][128 + hh] + b_ih[128 + hh] + b_hh[128 + hh];
        float go = gsm[row][192 + hh] + b_ih[192 + hh] + b_hh[192 + hh];
        float c = sigmoidf_(gi) * tanhf(gg);
        g_henc[(size_t)(i0 + row) * 64 + hh] = sigmoidf_(go) * tanhf(c);
    }
}

// ---------------- 7. decoder: gates = h_enc @ dec_W_ih.T, LSTM fused ----------------
__global__ __launch_bounds__(512) void dec_fused(const float* __restrict__ W,
                                                 const float* __restrict__ b_ih,
                                                 const float* __restrict__ b_hh,
                                                 float* __restrict__ out) {
    __shared__ union {
        struct { float As[16][64]; float Ws[16][513]; } in;
        float gsm[16][512];
    } sm;
    const int i0 = blockIdx.x * 16;
    const int tid = threadIdx.x;
    const int n = tid;

    for (int idx = tid; idx < 16 * 64; idx += 512)
        sm.in.As[idx >> 6][idx & 63] = g_henc[(size_t)(i0 + (idx >> 6)) * 64 + (idx & 63)];

    float acc[16];
#pragma unroll
    for (int r = 0; r < 16; r++) acc[r] = 0.f;

    for (int kt = 0; kt < 64; kt += 16) {
        __syncthreads();
        for (int f = tid; f < 16 * 512; f += 512) {
            int n2 = f >> 4, kk = f & 15;
            sm.in.Ws[kk][n2] = W[(size_t)n2 * 64 + kt + kk];
        }
        __syncthreads();
#pragma unroll
        for (int kk = 0; kk < 16; kk++) {
            float b = sm.in.Ws[kk][n];
#pragma unroll
            for (int r = 0; r < 16; r++) acc[r] += sm.in.As[r][kt + kk] * b;
        }
    }
    __syncthreads();
#pragma unroll
    for (int r = 0; r < 16; r++) sm.gsm[r][n] = acc[r];
    __syncthreads();

#pragma unroll
    for (int e = 0; e < 4; e++) {
        int idx = tid + e * 512;
        int row = idx >> 7, hh = idx & 127;
        float gi = sm.gsm[row][hh] + b_ih[hh] + b_hh[hh];
        float gg = sm.gsm[row][256 + hh] + b_ih[256 + hh] + b_hh[256 + hh];
        float go = sm.gsm[row][384 + hh] + b_ih[384 + hh] + b_hh[384 + hh];
        float c = sigmoidf_(gi) * tanhf(gg);
        out[(size_t)(i0 + row) * 128 + hh] = sigmoidf_(go) * tanhf(c);
    }
}

// ---------------- launch ----------------
extern "C" void kernel_launch(void* const* d_in, const int* in_sizes, int n_in,
                              void* d_out, int out_size) {
    const float* x = (const float*)d_in[0];
    const float* adj = (const float*)d_in[1];
    const float* fea_W = (const float*)d_in[2];
    const float* fea_b = (const float*)d_in[3];
    const float* gat_W = (const float*)d_in[4];
    const float* gat_a = (const float*)d_in[5];
    const float* enc_W_ih = (const float*)d_in[6];
    const float* enc_b_ih = (const float*)d_in[8];
    const float* enc_b_hh = (const float*)d_in[9];
    const float* dec_W_ih = (const float*)d_in[10];
    const float* dec_b_ih = (const float*)d_in[12];
    const float* dec_b_hh = (const float*)d_in[13];

    float* out = (float*)d_out;
    float* con_adj = out;
    float* att_adj = out + (size_t)NROWS * NROWS;

    cudaFuncSetAttribute(attn_mma_kernel, cudaFuncAttributeMaxDynamicSharedMemorySize, ATTN_SMEM);
    cudaFuncSetAttribute(syrk_mma_kernel, cudaFuncAttributeMaxDynamicSharedMemorySize, SYRK_SMEM);

    struct_kernel<<<NROWS / 16, 256>>>(x, fea_W, fea_b);                    // 1
    wh_s1s2_kernel<<<NROWS / 16, 256>>>(gat_W, gat_a);                      // 2
    vec_kernel<<<NROWS / 256, 256>>>();                                     // 3
    attn_mma_kernel<<<dim3(NROWS / 64, NSPLIT), 256, ATTN_SMEM>>>(adj);     // 4  <- ncu slot
    combine_kernel<<<NROWS * 32 / 256, 256>>>();                            // 5
    syrk_mma_kernel<<<2080, 512, SYRK_SMEM>>>(con_adj);                     // 6
    enc_fused<<<NROWS / 16, 256>>>(x, enc_W_ih, enc_b_ih, enc_b_hh);        // 7
    dec_fused<<<NROWS / 16, 512>>>(dec_W_ih, dec_b_ih, dec_b_hh, att_adj);  // 8
}

// round 14
// speedup vs baseline: 1.1335x; 1.0749x over previous
#include <cuda_runtime.h>
#include <cuda_bf16.h>
#include <cstdint>

#define NROWS 8192
#define IN_DIM 128
#define HID 64
#define NSPLIT 16
#define JSEG (NROWS / NSPLIT)

typedef unsigned long long ull;

// ---------------- scratch (static device globals; no allocation) ----------------
__device__ __align__(16) float g_struct[NROWS * HID];
__device__ __align__(16) __nv_bfloat16 g_Whh[NROWS * IN_DIM];
__device__ __align__(16) __nv_bfloat16 g_Whl[NROWS * IN_DIM];
__device__ __align__(16) float g_s1[NROWS];
__device__ __align__(16) float g_s2[NROWS];
__device__ __align__(16) float g_A[NROWS];
__device__ __align__(16) float g_B[NROWS];
__device__ __align__(16) float g_C[NROWS];
__device__ __align__(16) float g_D[NROWS];
__device__ unsigned g_s2max_bits = 0u;
__device__ __align__(16) float g_henc[NROWS * HID];
__device__ __align__(16) __nv_bfloat16 g_embh[NROWS * IN_DIM];
__device__ __align__(16) __nv_bfloat16 g_embl[NROWS * IN_DIM];
__device__ __align__(16) float g_pacc[NSPLIT * NROWS * IN_DIM];
__device__ __align__(16) float g_pden[NSPLIT * NROWS];

// ---------------- helpers ----------------
__device__ __forceinline__ float sigmoidf_(float x) { return 1.0f / (1.0f + __expf(-x)); }

__device__ __forceinline__ unsigned float_key(float f) {
    unsigned b = __float_as_uint(f);
    return (b & 0x80000000u) ? ~b : (b | 0x80000000u);
}
__device__ __forceinline__ float key_float(unsigned k) {
    unsigned b = (k & 0x80000000u) ? (k & 0x7fffffffu) : ~k;
    return __uint_as_float(b);
}
__device__ __forceinline__ uint32_t smem_u32(const void* p) {
    uint32_t a;
    asm("{ .reg .u64 t; cvta.to.shared.u64 t, %1; cvt.u32.u64 %0, t; }" : "=r"(a) : "l"(p));
    return a;
}

#define CP_ASYNC16(dst, src) asm volatile("cp.async.cg.shared.global [%0], [%1], 16;" :: "r"(dst), "l"(src))
#define CP_COMMIT() asm volatile("cp.async.commit_group;" ::: "memory")
#define CP_WAIT0() asm volatile("cp.async.wait_group 0;" ::: "memory")

// ---------------- mma.sync helpers (bf16, m16n8k16) ----------------
__device__ __forceinline__ void ldm_x4(uint32_t* a, uint32_t addr) {
    asm volatile("ldmatrix.sync.aligned.m8n8.x4.shared.b16 {%0,%1,%2,%3}, [%4];"
                 : "=r"(a[0]), "=r"(a[1]), "=r"(a[2]), "=r"(a[3]) : "r"(addr));
}
__device__ __forceinline__ void ldm_x4t(uint32_t* a, uint32_t addr) {
    asm volatile("ldmatrix.sync.aligned.m8n8.x4.trans.shared.b16 {%0,%1,%2,%3}, [%4];"
                 : "=r"(a[0]), "=r"(a[1]), "=r"(a[2]), "=r"(a[3]) : "r"(addr));
}
__device__ __forceinline__ void ldm_x2(uint32_t* b, uint32_t addr) {
    asm volatile("ldmatrix.sync.aligned.m8n8.x2.shared.b16 {%0,%1}, [%2];"
                 : "=r"(b[0]), "=r"(b[1]) : "r"(addr));
}
__device__ __forceinline__ void mma16816(float* d, const uint32_t* a, const uint32_t* b) {
    asm volatile("mma.sync.aligned.m16n8k16.row.col.f32.bf16.bf16.f32 "
                 "{%0,%1,%2,%3}, {%4,%5,%6,%7}, {%8,%9}, {%0,%1,%2,%3};"
                 : "+f"(d[0]), "+f"(d[1]), "+f"(d[2]), "+f"(d[3])
                 : "r"(a[0]), "r"(a[1]), "r"(a[2]), "r"(a[3]), "r"(b[0]), "r"(b[1]));
}

// ---------------- 1. structure = relu(x @ fea_W + fea_b) ----------------
__global__ __launch_bounds__(256) void struct_kernel(const float* __restrict__ A,
                                                     const float* __restrict__ W,
                                                     const float* __restrict__ bias) {
    __shared__ float As[16][128];
    const int i0 = blockIdx.x * 16;
    const int tid = threadIdx.x;
    const int n = tid & 63, rg = tid >> 6;

    for (int idx = tid; idx < 16 * 128; idx += 256)
        As[idx >> 7][idx & 127] = A[(size_t)(i0 + (idx >> 7)) * 128 + (idx & 127)];
    __syncthreads();

    float acc[4] = {0.f, 0.f, 0.f, 0.f};
#pragma unroll 4
    for (int k = 0; k < 128; k++) {
        float b = W[(size_t)k * 64 + n];
#pragma unroll
        for (int r = 0; r < 4; r++) acc[r] += As[rg * 4 + r][k] * b;
    }
    float bv = bias[n];
#pragma unroll
    for (int r = 0; r < 4; r++)
        g_struct[(size_t)(i0 + rg * 4 + r) * 64 + n] = fmaxf(acc[r] + bv, 0.f);
}

// ---------------- 2. Wh = structure @ gat_W (bf16 hi/lo), fused s1/s2/max(s2) ----------------
__global__ __launch_bounds__(256) void wh_s1s2_kernel(const float* __restrict__ W,
                                                      const float* __restrict__ gat_a) {
    __shared__ float As[16][64];
    __shared__ float r1[8][8], r2[8][8];
    const int i0 = blockIdx.x * 16;
    const int tid = threadIdx.x;
    const int n = tid & 127, rg = tid >> 7;

    for (int idx = tid; idx < 16 * 64; idx += 256)
        As[idx >> 6][idx & 63] = g_struct[(size_t)(i0 + (idx >> 6)) * 64 + (idx & 63)];
    __syncthreads();

    float acc[8];
#pragma unroll
    for (int r = 0; r < 8; r++) acc[r] = 0.f;
#pragma unroll 4
    for (int k = 0; k < 64; k++) {
        float b = W[(size_t)k * 128 + n];
#pragma unroll
        for (int r = 0; r < 8; r++) acc[r] += As[rg * 8 + r][k] * b;
    }
#pragma unroll
    for (int r = 0; r < 8; r++) {
        float v = acc[r];
        __nv_bfloat16 hi = __float2bfloat16(v);
        __nv_bfloat16 lo = __float2bfloat16(v - __bfloat162float(hi));
        g_Whh[(size_t)(i0 + rg * 8 + r) * 128 + n] = hi;
        g_Whl[(size_t)(i0 + rg * 8 + r) * 128 + n] = lo;
    }

    float a1v = gat_a[n], a2v = gat_a[128 + n];
    int warp = tid >> 5, lane = tid & 31;
#pragma unroll
    for (int r = 0; r < 8; r++) {
        float v1 = acc[r] * a1v, v2 = acc[r] * a2v;
#pragma unroll
        for (int off = 16; off; off >>= 1) {
            v1 += __shfl_xor_sync(0xffffffffu, v1, off);
            v2 += __shfl_xor_sync(0xffffffffu, v2, off);
        }
        if (lane == 0) { r1[warp][r] = v1; r2[warp][r] = v2; }
    }
    __syncthreads();
    if (tid < 16) {
        int rgg = tid >> 3, rr = tid & 7;
        float s1 = r1[rgg * 4 + 0][rr] + r1[rgg * 4 + 1][rr] + r1[rgg * 4 + 2][rr] + r1[rgg * 4 + 3][rr];
        float s2 = r2[rgg * 4 + 0][rr] + r2[rgg * 4 + 1][rr] + r2[rgg * 4 + 2][rr] + r2[rgg * 4 + 3][rr];
        g_s1[i0 + tid] = s1;
        g_s2[i0 + tid] = s2;
        float m = s2;
#pragma unroll
        for (int off = 8; off; off >>= 1) m = fmaxf(m, __shfl_xor_sync(0x0000ffffu, m, off));
        if (tid == 0) atomicMax(&g_s2max_bits, float_key(m));
    }
}

// ---------------- 3. precompute A,B,C,D ----------------
__global__ void vec_kernel() {
    int i = blockIdx.x * 256 + threadIdx.x;
    float s2max = key_float(g_s2max_bits);
    float t = g_s1[i] + s2max;
    float m = t > 0.f ? t : 0.2f * t;
    g_A[i] = expf(t - m);
    g_C[i] = expf(0.2f * t - m);
    float u = g_s2[i] - s2max;
    g_B[i] = expf(u);
    g_D[i] = expf(0.2f * u);
}

// ---------------- 4. attention partial: cp.async pipelined mma split-bf16 (measured 179us) ----------------
#define PLD 40
#define WLD 136
#define WHH_OFF(b) ((b) * 8704)
#define WHL_OFF(b) (17408 + (b) * 8704)
#define ADJ_OFF(b) (34816 + (b) * 9216)
#define PH_OFF 53248
#define PL_OFF 58368
#define S2BD_OFF(b) (63488 + (b) * 384)
#define SAC_OFF 64256
#define ATTN_SMEM 65024

__global__ __launch_bounds__(256) void attn_mma_kernel(const float* __restrict__ adj) {
    extern __shared__ __align__(16) char smem[];
    const uint32_t sb = smem_u32(smem);
    float* sac = (float*)(smem + SAC_OFF);   // s1[64], A[64], C[64]

    const int i0 = blockIdx.x * 64;
    const int jb = blockIdx.y * JSEG;
    const int tid = threadIdx.x;
    const int lane = tid & 31, wid = tid >> 5;
    const int wm = wid & 1, wn = wid >> 1;
    if (tid < 64) {
        sac[tid] = g_s1[i0 + tid];
        sac[64 + tid] = g_A[i0 + tid];
        sac[128 + tid] = g_C[i0 + tid];
    }

    const int c4 = (tid & 7) * 4;
    const int rp = tid >> 3;

    float d[2][4][4];
#pragma unroll
    for (int mt = 0; mt < 2; mt++)
#pragma unroll
        for (int nt = 0; nt < 4; nt++)
#pragma unroll
            for (int q = 0; q < 4; q++) d[mt][nt][q] = 0.f;
    float dsum[2] = {0.f, 0.f};

    const int whrow = tid >> 4, whch = tid & 15;
    const int adrow = tid >> 3, adch = tid & 7;

    auto issue_cp = [&](int t) {
        int b = t & 1;
        int jc = jb + t * 32;
#pragma unroll
        for (int e = 0; e < 2; e++) {
            int row = whrow + e * 16;
            CP_ASYNC16(sb + WHH_OFF(b) + row * 272 + whch * 16,
                       (const char*)g_Whh + ((size_t)(jc + row) * 128 + whch * 8) * 2);
            CP_ASYNC16(sb + WHL_OFF(b) + row * 272 + whch * 16,
                       (const char*)g_Whl + ((size_t)(jc + row) * 128 + whch * 8) * 2);
            int arow = adrow + e * 32;
            CP_ASYNC16(sb + ADJ_OFF(b) + arow * 144 + adch * 16,
                       (const char*)adj + ((size_t)(i0 + arow) * NROWS + jc + adch * 4) * 4);
        }
        if (tid < 24) {
            int arr = tid >> 3, sub = tid & 7;
            const float* src = arr == 0 ? g_s2 : (arr == 1 ? g_B : g_D);
            CP_ASYNC16(sb + S2BD_OFF(b) + arr * 128 + sub * 16,
                       (const char*)(src + jc + sub * 4));
        }
    };

    issue_cp(0);
    CP_COMMIT();

    const int T = JSEG / 32;
    for (int t = 0; t < T; t++) {
        const int b = t & 1;
        CP_WAIT0();
        __syncthreads();
        if (t + 1 < T) { issue_cp(t + 1); CP_COMMIT(); }

        // transform: adj smem -> p hi/lo bf16 tiles
        {
            const float* s2bd = (const float*)(smem + S2BD_OFF(b));
            float4 s2v = ((const float4*)s2bd)[tid & 7];
            float4 Bv = ((const float4*)(s2bd + 32))[tid & 7];
            float4 Dv = ((const float4*)(s2bd + 64))[tid & 7];
            const float* adjs = (const float*)(smem + ADJ_OFF(b));
#pragma unroll
            for (int rr = 0; rr < 2; rr++) {
                int r = rp * 2 + rr;
                float4 av = *(const float4*)&adjs[r * 36 + c4];
                float s1 = sac[r], Av = sac[64 + r], Cv = sac[128 + r];
                float pv[4];
                { float tt = s1 + s2v.x; pv[0] = (av.x > 0.f) ? (tt > 0.f ? Av * Bv.x : Cv * Dv.x) : 0.f; }
                { float tt = s1 + s2v.y; pv[1] = (av.y > 0.f) ? (tt > 0.f ? Av * Bv.y : Cv * Dv.y) : 0.f; }
                { float tt = s1 + s2v.z; pv[2] = (av.z > 0.f) ? (tt > 0.f ? Av * Bv.z : Cv * Dv.z) : 0.f; }
                { float tt = s1 + s2v.w; pv[3] = (av.w > 0.f) ? (tt > 0.f ? Av * Bv.w : Cv * Dv.w) : 0.f; }
                ushort4 h4, l4;
                unsigned short* hp = (unsigned short*)&h4;
                unsigned short* lp = (unsigned short*)&l4;
#pragma unroll
                for (int q = 0; q < 4; q++) {
                    __nv_bfloat16 hi = __float2bfloat16(pv[q]);
                    __nv_bfloat16 lo = __float2bfloat16(pv[q] - __bfloat162float(hi));
                    hp[q] = *(unsigned short*)&hi;
                    lp[q] = *(unsigned short*)&lo;
                }
                *(ushort4*)(smem + PH_OFF + (r * PLD + c4) * 2) = h4;
                *(ushort4*)(smem + PL_OFF + (r * PLD + c4) * 2) = l4;
                dsum[rr] += (pv[0] + pv[1]) + (pv[2] + pv[3]);
            }
        }
        __syncthreads();

        // mma: d += ph*Whh + pl*Whh + ph*Whl
        const uint32_t ph_b = sb + PH_OFF, pl_b = sb + PL_OFF;
        const uint32_t whh_b = sb + WHH_OFF(b), whl_b = sb + WHL_OFF(b);
#pragma unroll
        for (int ks = 0; ks < 2; ks++) {
            int k0 = ks * 16;
            uint32_t aph[2][4], apl[2][4], bhh[2][4], bhl[2][4];
#pragma unroll
            for (int mt = 0; mt < 2; mt++) {
                uint32_t off = ((wm * 32 + mt * 16 + (lane & 15)) * PLD + k0 + (lane >> 4) * 8) * 2;
                ldm_x4(aph[mt], ph_b + off);
                ldm_x4(apl[mt], pl_b + off);
            }
#pragma unroll
            for (int np = 0; np < 2; np++) {
                uint32_t off = ((k0 + (lane & 15)) * WLD + wn * 32 + np * 16 + (lane >> 4) * 8) * 2;
                ldm_x4t(bhh[np], whh_b + off);
                ldm_x4t(bhl[np], whl_b + off);
            }
#pragma unroll
            for (int mt = 0; mt < 2; mt++)
#pragma unroll
                for (int np = 0; np < 2; np++)
#pragma unroll
                    for (int h = 0; h < 2; h++) {
                        int nt = np * 2 + h;
                        mma16816(d[mt][nt], aph[mt], &bhh[np][h * 2]);
                        mma16816(d[mt][nt], apl[mt], &bhh[np][h * 2]);
                        mma16816(d[mt][nt], aph[mt], &bhl[np][h * 2]);
                    }
        }
    }

#pragma unroll
    for (int off = 4; off; off >>= 1) {
        dsum[0] += __shfl_down_sync(0xffffffffu, dsum[0], off, 8);
        dsum[1] += __shfl_down_sync(0xffffffffu, dsum[1], off, 8);
    }
    if ((tid & 7) == 0) {
        g_pden[(size_t)blockIdx.y * NROWS + i0 + rp * 2] = dsum[0];
        g_pden[(size_t)blockIdx.y * NROWS + i0 + rp * 2 + 1] = dsum[1];
    }

    float* pa = g_pacc + (size_t)blockIdx.y * NROWS * IN_DIM;
    const int g = lane >> 2, tig = lane & 3;
#pragma unroll
    for (int mt = 0; mt < 2; mt++) {
        int r0 = i0 + wm * 32 + mt * 16 + g;
#pragma unroll
        for (int nt = 0; nt < 4; nt++) {
            int col = wn * 32 + nt * 8 + tig * 2;
            *(float2*)&pa[(size_t)r0 * IN_DIM + col] = make_float2(d[mt][nt][0], d[mt][nt][1]);
            *(float2*)&pa[(size_t)(r0 + 8) * IN_DIM + col] = make_float2(d[mt][nt][2], d[mt][nt][3]);
        }
    }
}

// ---------------- 4b. combine: emb = elu(sum/den), split to bf16 hi+lo ----------------
__global__ __launch_bounds__(256) void combine_kernel() {
    int idx = blockIdx.x * 256 + threadIdx.x;
    int row = idx >> 5;
    float den = 0.f;
    float4 acc = make_float4(0.f, 0.f, 0.f, 0.f);
#pragma unroll
    for (int s = 0; s < NSPLIT; s++) {
        den += g_pden[(size_t)s * NROWS + row];
        float4 v = ((const float4*)g_pacc)[(size_t)s * NROWS * 32 + idx];
        acc.x += v.x; acc.y += v.y; acc.z += v.z; acc.w += v.w;
    }
    float inv = 1.0f / den;
    float o[4] = {acc.x * inv, acc.y * inv, acc.z * inv, acc.w * inv};
    __nv_bfloat16 hi[4], lo[4];
#pragma unroll
    for (int j = 0; j < 4; j++) {
        o[j] = o[j] > 0.f ? o[j] : expm1f(o[j]);
        hi[j] = __float2bfloat16(o[j]);
        lo[j] = __float2bfloat16(o[j] - __bfloat162float(hi[j]));
    }
    *(ull*)&g_embh[(size_t)idx * 4] = *(const ull*)hi;
    *(ull*)&g_embl[(size_t)idx * 4] = *(const ull*)lo;
}

// ---------------- 5. con_adj = emb @ emb.T via mma.sync bf16 split (R9 best: rest=293) ----------------
#define LDB 136
#define TILE_ELEMS (128 * LDB)
#define SYRK_SMEM (4 * TILE_ELEMS * 2)

__device__ __forceinline__ void syrk_mma_phase(
    const __nv_bfloat16* Ah, const __nv_bfloat16* Al,
    const __nv_bfloat16* Bh, const __nv_bfloat16* Bl,
    int m0, int n0, int lane, float d[4][4][4]) {
#pragma unroll
    for (int pass = 0; pass < 3; pass++) {
        const __nv_bfloat16* Ap = (pass == 2) ? Al : Ah;
        const __nv_bfloat16* Bp = (pass == 1) ? Bl : Bh;
        uint32_t a_base = smem_u32(Ap);
        uint32_t b_base = smem_u32(Bp);
#pragma unroll
        for (int ks = 0; ks < 8; ks++) {
            int k0 = ks * 16;
            uint32_t afr[4][4], bfr[4][2];
#pragma unroll
            for (int mt = 0; mt < 4; mt++) {
                int row = m0 + mt * 16 + (lane & 15);
                int col = k0 + (lane >> 4) * 8;
                ldm_x4(afr[mt], a_base + (row * LDB + col) * 2);
            }
#pragma unroll
            for (int nt = 0; nt < 4; nt++) {
                int row = n0 + nt * 8 + (lane & 7);
                int col = k0 + ((lane >> 3) & 1) * 8;
                ldm_x2(bfr[nt], b_base + (row * LDB + col) * 2);
            }
#pragma unroll
            for (int mt = 0; mt < 4; mt++)
#pragma unroll
                for (int nt = 0; nt < 4; nt++)
                    mma16816(d[mt][nt], afr[mt], bfr[nt]);
        }
    }
}

__global__ __launch_bounds__(256) void syrk_mma_kernel(float* __restrict__ out) {
    const int bi = blockIdx.y, bj = blockIdx.x;
    if (bj < bi) return;
    extern __shared__ __nv_bfloat16 sm[];
    __nv_bfloat16* Ah = sm;
    __nv_bfloat16* Al = Ah + TILE_ELEMS;
    __nv_bfloat16* Bh = Al + TILE_ELEMS;
    __nv_bfloat16* Bl = Bh + TILE_ELEMS;

    const int tid = threadIdx.x;
    const int lane = tid & 31, wid = tid >> 5;
    const int i0 = bi * 128, j0 = bj * 128;
    const int m0 = (wid & 1) * 64, n0 = (wid >> 1) * 32;
    const int g = lane >> 2, tig = lane & 3;

    const uint4* EH = (const uint4*)g_embh;
    const uint4* EL = (const uint4*)g_embl;
#pragma unroll
    for (int e = 0; e < 8; e++) {
        int idx = tid + e * 256;
        int row = idx >> 4, ch = idx & 15;
        *(uint4*)&Ah[row * LDB + ch * 8] = EH[(size_t)(i0 + row) * 16 + ch];
        *(uint4*)&Al[row * LDB + ch * 8] = EL[(size_t)(i0 + row) * 16 + ch];
        *(uint4*)&Bh[row * LDB + ch * 8] = EH[(size_t)(j0 + row) * 16 + ch];
        *(uint4*)&Bl[row * LDB + ch * 8] = EL[(size_t)(j0 + row) * 16 + ch];
    }
    __syncthreads();

    float d[4][4][4];
#pragma unroll
    for (int mt = 0; mt < 4; mt++)
#pragma unroll
        for (int nt = 0; nt < 4; nt++)
#pragma unroll
            for (int q = 0; q < 4; q++) d[mt][nt][q] = 0.f;

    syrk_mma_phase(Ah, Al, Bh, Bl, m0, n0, lane, d);

#pragma unroll
    for (int mt = 0; mt < 4; mt++) {
        int r0 = i0 + m0 + mt * 16 + g;
#pragma unroll
        for (int nt = 0; nt < 4; nt++) {
            int c0 = j0 + n0 + nt * 8 + tig * 2;
            *(float2*)&out[(size_t)r0 * NROWS + c0] = make_float2(d[mt][nt][0], d[mt][nt][1]);
            *(float2*)&out[(size_t)(r0 + 8) * NROWS + c0] = make_float2(d[mt][nt][2], d[mt][nt][3]);
        }
    }

    if (bi != bj) {
#pragma unroll
        for (int mt = 0; mt < 4; mt++)
#pragma unroll
            for (int nt = 0; nt < 4; nt++)
#pragma unroll
                for (int q = 0; q < 4; q++) d[mt][nt][q] = 0.f;

        syrk_mma_phase(Bh, Bl, Ah, Al, m0, n0, lane, d);

#pragma unroll
        for (int mt = 0; mt < 4; mt++) {
            int r0 = j0 + m0 + mt * 16 + g;
#pragma unroll
            for (int nt = 0; nt < 4; nt++) {
                int c0 = i0 + n0 + nt * 8 + tig * 2;
                *(float2*)&out[(size_t)r0 * NROWS + c0] = make_float2(d[mt][nt][0], d[mt][nt][1]);
                *(float2*)&out[(size_t)(r0 + 8) * NROWS + c0] = make_float2(d[mt][nt][2], d[mt][nt][3]);
            }
        }
    }
}

// ---------------- 6. encoder: gates = x @ enc_W_ih.T, LSTM fused ----------------
__global__ __launch_bounds__(256) void enc_fused(const float* __restrict__ x,
                                                 const float* __restrict__ W,
                                                 const float* __restrict__ b_ih,
                                                 const float* __restrict__ b_hh) {
    __shared__ float As[16][128];
    __shared__ float Ws[16][257];
    __shared__ float gsm[16][256];
    const int i0 = blockIdx.x * 16;
    const int tid = threadIdx.x;
    const int n = tid;

    for (int idx = tid; idx < 16 * 128; idx += 256)
        As[idx >> 7][idx & 127] = x[(size_t)(i0 + (idx >> 7)) * 128 + (idx & 127)];

    float acc[16];
#pragma unroll
    for (int r = 0; r < 16; r++) acc[r] = 0.f;

    for (int kt = 0; kt < 128; kt += 16) {
        __syncthreads();
        for (int f = tid; f < 16 * 256; f += 256) {
            int n2 = f >> 4, kk = f & 15;
            Ws[kk][n2] = W[(size_t)n2 * 128 + kt + kk];
        }
        __syncthreads();
#pragma unroll
        for (int kk = 0; kk < 16; kk++) {
            float b = Ws[kk][n];
#pragma unroll
            for (int r = 0; r < 16; r++) acc[r] += As[r][kt + kk] * b;
        }
    }
    __syncthreads();
#pragma unroll
    for (int r = 0; r < 16; r++) gsm[r][n] = acc[r];
    __syncthreads();

#pragma unroll
    for (int e = 0; e < 4; e++) {
        int idx = tid + e * 256;
        int row = idx >> 6, hh = idx & 63;
        float gi = gsm[row][hh] + b_ih[hh] + b_hh[hh];
        float gg = gsm[row][128 + hh] + b_ih[128 + hh] + b_hh[128 + hh];
        float go = gsm[row][192 + hh] + b_ih[192 + hh] + b_hh[192 + hh];
        float c = sigmoidf_(gi) * tanhf(gg);
        g_henc[(size_t)(i0 + row) * 64 + hh] = sigmoidf_(go) * tanhf(c);
    }
}

// ---------------- 7. decoder: gates = h_enc @ dec_W_ih.T, LSTM fused ----------------
__global__ __launch_bounds__(512) void dec_fused(const float* __restrict__ W,
                                                 const float* __restrict__ b_ih,
                                                 const float* __restrict__ b_hh,
                                                 float* __restrict__ out) {
    __shared__ union {
        struct { float As[16][64]; float Ws[16][513]; } in;
        float gsm[16][512];
    } sm;
    const int i0 = blockIdx.x * 16;
    const int tid = threadIdx.x;
    const int n = tid;

    for (int idx = tid; idx < 16 * 64; idx += 512)
        sm.in.As[idx >> 6][idx & 63] = g_henc[(size_t)(i0 + (idx >> 6)) * 64 + (idx & 63)];

    float acc[16];
#pragma unroll
    for (int r = 0; r < 16; r++) acc[r] = 0.f;

    for (int kt = 0; kt < 64; kt += 16) {
        __syncthreads();
        for (int f = tid; f < 16 * 512; f += 512) {
            int n2 = f >> 4, kk = f & 15;
            sm.in.Ws[kk][n2] = W[(size_t)n2 * 64 + kt + kk];
        }
        __syncthreads();
#pragma unroll
        for (int kk = 0; kk < 16; kk++) {
            float b = sm.in.Ws[kk][n];
#pragma unroll
            for (int r = 0; r < 16; r++) acc[r] += sm.in.As[r][kt + kk] * b;
        }
    }
    __syncthreads();
#pragma unroll
    for (int r = 0; r < 16; r++) sm.gsm[r][n] = acc[r];
    __syncthreads();

#pragma unroll
    for (int e = 0; e < 4; e++) {
        int idx = tid + e * 512;
        int row = idx >> 7, hh = idx & 127;
        float gi = sm.gsm[row][hh] + b_ih[hh] + b_hh[hh];
        float gg = sm.gsm[row][256 + hh] + b_ih[256 + hh] + b_hh[256 + hh];
        float go = sm.gsm[row][384 + hh] + b_ih[384 + hh] + b_hh[384 + hh];
        float c = sigmoidf_(gi) * tanhf(gg);
        out[(size_t)(i0 + row) * 128 + hh] = sigmoidf_(go) * tanhf(c);
    }
}

// ---------------- launch ----------------
extern "C" void kernel_launch(void* const* d_in, const int* in_sizes, int n_in,
                              void* d_out, int out_size) {
    const float* x = (const float*)d_in[0];
    const float* adj = (const float*)d_in[1];
    const float* fea_W = (const float*)d_in[2];
    const float* fea_b = (const float*)d_in[3];
    const float* gat_W = (const float*)d_in[4];
    const float* gat_a = (const float*)d_in[5];
    const float* enc_W_ih = (const float*)d_in[6];
    const float* enc_b_ih = (const float*)d_in[8];
    const float* enc_b_hh = (const float*)d_in[9];
    const float* dec_W_ih = (const float*)d_in[10];
    const float* dec_b_ih = (const float*)d_in[12];
    const float* dec_b_hh = (const float*)d_in[13];

    float* out = (float*)d_out;
    float* con_adj = out;
    float* att_adj = out + (size_t)NROWS * NROWS;

    cudaFuncSetAttribute(attn_mma_kernel, cudaFuncAttributeMaxDynamicSharedMemorySize, ATTN_SMEM);
    cudaFuncSetAttribute(syrk_mma_kernel, cudaFuncAttributeMaxDynamicSharedMemorySize, SYRK_SMEM);

    struct_kernel<<<NROWS / 16, 256>>>(x, fea_W, fea_b);                    // 1
    wh_s1s2_kernel<<<NROWS / 16, 256>>>(gat_W, gat_a);                      // 2
    vec_kernel<<<NROWS / 256, 256>>>();                                     // 3
    attn_mma_kernel<<<dim3(NROWS / 64, NSPLIT), 256, ATTN_SMEM>>>(adj);     // 4  <- ncu slot
    combine_kernel<<<NROWS * 32 / 256, 256>>>();                            // 5
    syrk_mma_kernel<<<dim3(64, 64), 256, SYRK_SMEM>>>(con_adj);             // 6
    enc_fused<<<NROWS / 16, 256>>>(x, enc_W_ih, enc_b_ih, enc_b_hh);        // 7
    dec_fused<<<NROWS / 16, 512>>>(dec_W_ih, dec_b_ih, dec_b_hh, att_adj);  // 8
}

// round 15
// speedup vs baseline: 1.1384x; 1.0043x over previous
#include <cuda_runtime.h>
#include <cuda_bf16.h>
#include <cstdint>

#define NROWS 8192
#define IN_DIM 128
#define HID 64
#define NSPLIT 16
#define JSEG (NROWS / NSPLIT)

typedef unsigned long long ull;

// ---------------- scratch (static device globals; no allocation) ----------------
__device__ __align__(16) float g_struct[NROWS * HID];
__device__ __align__(16) __nv_bfloat16 g_Whh[NROWS * IN_DIM];
__device__ __align__(16) __nv_bfloat16 g_Whl[NROWS * IN_DIM];
__device__ __align__(16) float g_s1[NROWS];
__device__ __align__(16) float g_s2[NROWS];
__device__ __align__(16) float g_A[NROWS];
__device__ __align__(16) float g_B[NROWS];
__device__ __align__(16) float g_C[NROWS];
__device__ __align__(16) float g_D[NROWS];
__device__ unsigned g_s2max_bits = 0u;
__device__ __align__(16) float g_henc[NROWS * HID];
__device__ __align__(16) __nv_bfloat16 g_embh[NROWS * IN_DIM];
__device__ __align__(16) __nv_bfloat16 g_embl[NROWS * IN_DIM];
__device__ __align__(16) float g_pacc[NSPLIT * NROWS * IN_DIM];
__device__ __align__(16) float g_pden[NSPLIT * NROWS];

// ---------------- helpers ----------------
__device__ __forceinline__ float sigmoidf_(float x) { return 1.0f / (1.0f + __expf(-x)); }

__device__ __forceinline__ unsigned float_key(float f) {
    unsigned b = __float_as_uint(f);
    return (b & 0x80000000u) ? ~b : (b | 0x80000000u);
}
__device__ __forceinline__ float key_float(unsigned k) {
    unsigned b = (k & 0x80000000u) ? (k & 0x7fffffffu) : ~k;
    return __uint_as_float(b);
}
__device__ __forceinline__ uint32_t smem_u32(const void* p) {
    uint32_t a;
    asm("{ .reg .u64 t; cvta.to.shared.u64 t, %1; cvt.u32.u64 %0, t; }" : "=r"(a) : "l"(p));
    return a;
}

#define CP_ASYNC16(dst, src) asm volatile("cp.async.cg.shared.global [%0], [%1], 16;" :: "r"(dst), "l"(src))
#define CP_COMMIT() asm volatile("cp.async.commit_group;" ::: "memory")
#define CP_WAIT0() asm volatile("cp.async.wait_group 0;" ::: "memory")

// ---------------- mma.sync helpers (bf16, m16n8k16) ----------------
__device__ __forceinline__ void ldm_x4(uint32_t* a, uint32_t addr) {
    asm volatile("ldmatrix.sync.aligned.m8n8.x4.shared.b16 {%0,%1,%2,%3}, [%4];"
                 : "=r"(a[0]), "=r"(a[1]), "=r"(a[2]), "=r"(a[3]) : "r"(addr));
}
__device__ __forceinline__ void ldm_x4t(uint32_t* a, uint32_t addr) {
    asm volatile("ldmatrix.sync.aligned.m8n8.x4.trans.shared.b16 {%0,%1,%2,%3}, [%4];"
                 : "=r"(a[0]), "=r"(a[1]), "=r"(a[2]), "=r"(a[3]) : "r"(addr));
}
__device__ __forceinline__ void ldm_x2(uint32_t* b, uint32_t addr) {
    asm volatile("ldmatrix.sync.aligned.m8n8.x2.shared.b16 {%0,%1}, [%2];"
                 : "=r"(b[0]), "=r"(b[1]) : "r"(addr));
}
__device__ __forceinline__ void mma16816(float* d, const uint32_t* a, const uint32_t* b) {
    asm volatile("mma.sync.aligned.m16n8k16.row.col.f32.bf16.bf16.f32 "
                 "{%0,%1,%2,%3}, {%4,%5,%6,%7}, {%8,%9}, {%0,%1,%2,%3};"
                 : "+f"(d[0]), "+f"(d[1]), "+f"(d[2]), "+f"(d[3])
                 : "r"(a[0]), "r"(a[1]), "r"(a[2]), "r"(a[3]), "r"(b[0]), "r"(b[1]));
}

// ---------------- 1. structure = relu(x @ fea_W + fea_b) ----------------
__global__ __launch_bounds__(256) void struct_kernel(const float* __restrict__ A,
                                                     const float* __restrict__ W,
                                                     const float* __restrict__ bias) {
    __shared__ float As[16][128];
    const int i0 = blockIdx.x * 16;
    const int tid = threadIdx.x;
    const int n = tid & 63, rg = tid >> 6;

    for (int idx = tid; idx < 16 * 128; idx += 256)
        As[idx >> 7][idx & 127] = A[(size_t)(i0 + (idx >> 7)) * 128 + (idx & 127)];
    __syncthreads();

    float acc[4] = {0.f, 0.f, 0.f, 0.f};
#pragma unroll 4
    for (int k = 0; k < 128; k++) {
        float b = W[(size_t)k * 64 + n];
#pragma unroll
        for (int r = 0; r < 4; r++) acc[r] += As[rg * 4 + r][k] * b;
    }
    float bv = bias[n];
#pragma unroll
    for (int r = 0; r < 4; r++)
        g_struct[(size_t)(i0 + rg * 4 + r) * 64 + n] = fmaxf(acc[r] + bv, 0.f);
}

// ---------------- 2. Wh = structure @ gat_W (bf16 hi/lo), fused s1/s2/max(s2) ----------------
__global__ __launch_bounds__(256) void wh_s1s2_kernel(const float* __restrict__ W,
                                                      const float* __restrict__ gat_a) {
    __shared__ float As[16][64];
    __shared__ float r1[8][8], r2[8][8];
    const int i0 = blockIdx.x * 16;
    const int tid = threadIdx.x;
    const int n = tid & 127, rg = tid >> 7;

    for (int idx = tid; idx < 16 * 64; idx += 256)
        As[idx >> 6][idx & 63] = g_struct[(size_t)(i0 + (idx >> 6)) * 64 + (idx & 63)];
    __syncthreads();

    float acc[8];
#pragma unroll
    for (int r = 0; r < 8; r++) acc[r] = 0.f;
#pragma unroll 4
    for (int k = 0; k < 64; k++) {
        float b = W[(size_t)k * 128 + n];
#pragma unroll
        for (int r = 0; r < 8; r++) acc[r] += As[rg * 8 + r][k] * b;
    }
#pragma unroll
    for (int r = 0; r < 8; r++) {
        float v = acc[r];
        __nv_bfloat16 hi = __float2bfloat16(v);
        __nv_bfloat16 lo = __float2bfloat16(v - __bfloat162float(hi));
        g_Whh[(size_t)(i0 + rg * 8 + r) * 128 + n] = hi;
        g_Whl[(size_t)(i0 + rg * 8 + r) * 128 + n] = lo;
    }

    float a1v = gat_a[n], a2v = gat_a[128 + n];
    int warp = tid >> 5, lane = tid & 31;
#pragma unroll
    for (int r = 0; r < 8; r++) {
        float v1 = acc[r] * a1v, v2 = acc[r] * a2v;
#pragma unroll
        for (int off = 16; off; off >>= 1) {
            v1 += __shfl_xor_sync(0xffffffffu, v1, off);
            v2 += __shfl_xor_sync(0xffffffffu, v2, off);
        }
        if (lane == 0) { r1[warp][r] = v1; r2[warp][r] = v2; }
    }
    __syncthreads();
    if (tid < 16) {
        int rgg = tid >> 3, rr = tid & 7;
        float s1 = r1[rgg * 4 + 0][rr] + r1[rgg * 4 + 1][rr] + r1[rgg * 4 + 2][rr] + r1[rgg * 4 + 3][rr];
        float s2 = r2[rgg * 4 + 0][rr] + r2[rgg * 4 + 1][rr] + r2[rgg * 4 + 2][rr] + r2[rgg * 4 + 3][rr];
        g_s1[i0 + tid] = s1;
        g_s2[i0 + tid] = s2;
        float m = s2;
#pragma unroll
        for (int off = 8; off; off >>= 1) m = fmaxf(m, __shfl_xor_sync(0x0000ffffu, m, off));
        if (tid == 0) atomicMax(&g_s2max_bits, float_key(m));
    }
}

// ---------------- 3. precompute A,B,C,D ----------------
__global__ void vec_kernel() {
    int i = blockIdx.x * 256 + threadIdx.x;
    float s2max = key_float(g_s2max_bits);
    float t = g_s1[i] + s2max;
    float m = t > 0.f ? t : 0.2f * t;
    g_A[i] = expf(t - m);
    g_C[i] = expf(0.2f * t - m);
    float u = g_s2[i] - s2max;
    g_B[i] = expf(u);
    g_D[i] = expf(0.2f * u);
}

// ---------------- 4. attention partial: cp.async pipelined mma split-bf16 (measured 179us) ----------------
#define PLD 40
#define WLD 136
#define WHH_OFF(b) ((b) * 8704)
#define WHL_OFF(b) (17408 + (b) * 8704)
#define ADJ_OFF(b) (34816 + (b) * 9216)
#define PH_OFF 53248
#define PL_OFF 58368
#define S2BD_OFF(b) (63488 + (b) * 384)
#define SAC_OFF 64256
#define ATTN_SMEM 65024

__global__ __launch_bounds__(256) void attn_mma_kernel(const float* __restrict__ adj) {
    extern __shared__ __align__(16) char smem[];
    const uint32_t sb = smem_u32(smem);
    float* sac = (float*)(smem + SAC_OFF);   // s1[64], A[64], C[64]

    const int i0 = blockIdx.x * 64;
    const int jb = blockIdx.y * JSEG;
    const int tid = threadIdx.x;
    const int lane = tid & 31, wid = tid >> 5;
    const int wm = wid & 1, wn = wid >> 1;
    if (tid < 64) {
        sac[tid] = g_s1[i0 + tid];
        sac[64 + tid] = g_A[i0 + tid];
        sac[128 + tid] = g_C[i0 + tid];
    }

    const int c4 = (tid & 7) * 4;
    const int rp = tid >> 3;

    float d[2][4][4];
#pragma unroll
    for (int mt = 0; mt < 2; mt++)
#pragma unroll
        for (int nt = 0; nt < 4; nt++)
#pragma unroll
            for (int q = 0; q < 4; q++) d[mt][nt][q] = 0.f;
    float dsum[2] = {0.f, 0.f};

    const int whrow = tid >> 4, whch = tid & 15;
    const int adrow = tid >> 3, adch = tid & 7;

    auto issue_cp = [&](int t) {
        int b = t & 1;
        int jc = jb + t * 32;
#pragma unroll
        for (int e = 0; e < 2; e++) {
            int row = whrow + e * 16;
            CP_ASYNC16(sb + WHH_OFF(b) + row * 272 + whch * 16,
                       (const char*)g_Whh + ((size_t)(jc + row) * 128 + whch * 8) * 2);
            CP_ASYNC16(sb + WHL_OFF(b) + row * 272 + whch * 16,
                       (const char*)g_Whl + ((size_t)(jc + row) * 128 + whch * 8) * 2);
            int arow = adrow + e * 32;
            CP_ASYNC16(sb + ADJ_OFF(b) + arow * 144 + adch * 16,
                       (const char*)adj + ((size_t)(i0 + arow) * NROWS + jc + adch * 4) * 4);
        }
        if (tid < 24) {
            int arr = tid >> 3, sub = tid & 7;
            const float* src = arr == 0 ? g_s2 : (arr == 1 ? g_B : g_D);
            CP_ASYNC16(sb + S2BD_OFF(b) + arr * 128 + sub * 16,
                       (const char*)(src + jc + sub * 4));
        }
    };

    issue_cp(0);
    CP_COMMIT();

    const int T = JSEG / 32;
    for (int t = 0; t < T; t++) {
        const int b = t & 1;
        CP_WAIT0();
        __syncthreads();
        if (t + 1 < T) { issue_cp(t + 1); CP_COMMIT(); }

        // transform: adj smem -> p hi/lo bf16 tiles
        {
            const float* s2bd = (const float*)(smem + S2BD_OFF(b));
            float4 s2v = ((const float4*)s2bd)[tid & 7];
            float4 Bv = ((const float4*)(s2bd + 32))[tid & 7];
            float4 Dv = ((const float4*)(s2bd + 64))[tid & 7];
            const float* adjs = (const float*)(smem + ADJ_OFF(b));
#pragma unroll
            for (int rr = 0; rr < 2; rr++) {
                int r = rp * 2 + rr;
                float4 av = *(const float4*)&adjs[r * 36 + c4];
                float s1 = sac[r], Av = sac[64 + r], Cv = sac[128 + r];
                float pv[4];
                { float tt = s1 + s2v.x; pv[0] = (av.x > 0.f) ? (tt > 0.f ? Av * Bv.x : Cv * Dv.x) : 0.f; }
                { float tt = s1 + s2v.y; pv[1] = (av.y > 0.f) ? (tt > 0.f ? Av * Bv.y : Cv * Dv.y) : 0.f; }
                { float tt = s1 + s2v.z; pv[2] = (av.z > 0.f) ? (tt > 0.f ? Av * Bv.z : Cv * Dv.z) : 0.f; }
                { float tt = s1 + s2v.w; pv[3] = (av.w > 0.f) ? (tt > 0.f ? Av * Bv.w : Cv * Dv.w) : 0.f; }
                ushort4 h4, l4;
                unsigned short* hp = (unsigned short*)&h4;
                unsigned short* lp = (unsigned short*)&l4;
#pragma unroll
                for (int q = 0; q < 4; q++) {
                    __nv_bfloat16 hi = __float2bfloat16(pv[q]);
                    __nv_bfloat16 lo = __float2bfloat16(pv[q] - __bfloat162float(hi));
                    hp[q] = *(unsigned short*)&hi;
                    lp[q] = *(unsigned short*)&lo;
                }
                *(ushort4*)(smem + PH_OFF + (r * PLD + c4) * 2) = h4;
                *(ushort4*)(smem + PL_OFF + (r * PLD + c4) * 2) = l4;
                dsum[rr] += (pv[0] + pv[1]) + (pv[2] + pv[3]);
            }
        }
        __syncthreads();

        // mma: d += ph*Whh + pl*Whh + ph*Whl
        const uint32_t ph_b = sb + PH_OFF, pl_b = sb + PL_OFF;
        const uint32_t whh_b = sb + WHH_OFF(b), whl_b = sb + WHL_OFF(b);
#pragma unroll
        for (int ks = 0; ks < 2; ks++) {
            int k0 = ks * 16;
            uint32_t aph[2][4], apl[2][4], bhh[2][4], bhl[2][4];
#pragma unroll
            for (int mt = 0; mt < 2; mt++) {
                uint32_t off = ((wm * 32 + mt * 16 + (lane & 15)) * PLD + k0 + (lane >> 4) * 8) * 2;
                ldm_x4(aph[mt], ph_b + off);
                ldm_x4(apl[mt], pl_b + off);
            }
#pragma unroll
            for (int np = 0; np < 2; np++) {
                uint32_t off = ((k0 + (lane & 15)) * WLD + wn * 32 + np * 16 + (lane >> 4) * 8) * 2;
                ldm_x4t(bhh[np], whh_b + off);
                ldm_x4t(bhl[np], whl_b + off);
            }
#pragma unroll
            for (int mt = 0; mt < 2; mt++)
#pragma unroll
                for (int np = 0; np < 2; np++)
#pragma unroll
                    for (int h = 0; h < 2; h++) {
                        int nt = np * 2 + h;
                        mma16816(d[mt][nt], aph[mt], &bhh[np][h * 2]);
                        mma16816(d[mt][nt], apl[mt], &bhh[np][h * 2]);
                        mma16816(d[mt][nt], aph[mt], &bhl[np][h * 2]);
                    }
        }
    }

#pragma unroll
    for (int off = 4; off; off >>= 1) {
        dsum[0] += __shfl_down_sync(0xffffffffu, dsum[0], off, 8);
        dsum[1] += __shfl_down_sync(0xffffffffu, dsum[1], off, 8);
    }
    if ((tid & 7) == 0) {
        g_pden[(size_t)blockIdx.y * NROWS + i0 + rp * 2] = dsum[0];
        g_pden[(size_t)blockIdx.y * NROWS + i0 + rp * 2 + 1] = dsum[1];
    }

    float* pa = g_pacc + (size_t)blockIdx.y * NROWS * IN_DIM;
    const int g = lane >> 2, tig = lane & 3;
#pragma unroll
    for (int mt = 0; mt < 2; mt++) {
        int r0 = i0 + wm * 32 + mt * 16 + g;
#pragma unroll
        for (int nt = 0; nt < 4; nt++) {
            int col = wn * 32 + nt * 8 + tig * 2;
            *(float2*)&pa[(size_t)r0 * IN_DIM + col] = make_float2(d[mt][nt][0], d[mt][nt][1]);
            *(float2*)&pa[(size_t)(r0 + 8) * IN_DIM + col] = make_float2(d[mt][nt][2], d[mt][nt][3]);
        }
    }
}

// ---------------- 4b. combine: emb = elu(sum/den), split to bf16 hi+lo ----------------
__global__ __launch_bounds__(256) void combine_kernel() {
    int idx = blockIdx.x * 256 + threadIdx.x;
    int row = idx >> 5;
    float den = 0.f;
    float4 acc = make_float4(0.f, 0.f, 0.f, 0.f);
#pragma unroll
    for (int s = 0; s < NSPLIT; s++) {
        den += g_pden[(size_t)s * NROWS + row];
        float4 v = ((const float4*)g_pacc)[(size_t)s * NROWS * 32 + idx];
        acc.x += v.x; acc.y += v.y; acc.z += v.z; acc.w += v.w;
    }
    float inv = 1.0f / den;
    float o[4] = {acc.x * inv, acc.y * inv, acc.z * inv, acc.w * inv};
    __nv_bfloat16 hi[4], lo[4];
#pragma unroll
    for (int j = 0; j < 4; j++) {
        o[j] = o[j] > 0.f ? o[j] : expm1f(o[j]);
        hi[j] = __float2bfloat16(o[j]);
        lo[j] = __float2bfloat16(o[j] - __bfloat162float(hi[j]));
    }
    *(ull*)&g_embh[(size_t)idx * 4] = *(const ull*)hi;
    *(ull*)&g_embl[(size_t)idx * 4] = *(const ull*)lo;
}

// ---------------- 5. con_adj = emb @ emb.T via mma.sync bf16 split (R9 best: rest=293) ----------------
#define LDB 136
#define TILE_ELEMS (128 * LDB)
#define SYRK_SMEM (4 * TILE_ELEMS * 2)

__device__ __forceinline__ void syrk_mma_phase(
    const __nv_bfloat16* Ah, const __nv_bfloat16* Al,
    const __nv_bfloat16* Bh, const __nv_bfloat16* Bl,
    int m0, int n0, int lane, float d[4][4][4]) {
#pragma unroll
    for (int pass = 0; pass < 3; pass++) {
        const __nv_bfloat16* Ap = (pass == 2) ? Al : Ah;
        const __nv_bfloat16* Bp = (pass == 1) ? Bl : Bh;
        uint32_t a_base = smem_u32(Ap);
        uint32_t b_base = smem_u32(Bp);
#pragma unroll
        for (int ks = 0; ks < 8; ks++) {
            int k0 = ks * 16;
            uint32_t afr[4][4], bfr[4][2];
#pragma unroll
            for (int mt = 0; mt < 4; mt++) {
                int row = m0 + mt * 16 + (lane & 15);
                int col = k0 + (lane >> 4) * 8;
                ldm_x4(afr[mt], a_base + (row * LDB + col) * 2);
            }
#pragma unroll
            for (int nt = 0; nt < 4; nt++) {
                int row = n0 + nt * 8 + (lane & 7);
                int col = k0 + ((lane >> 3) & 1) * 8;
                ldm_x2(bfr[nt], b_base + (row * LDB + col) * 2);
            }
#pragma unroll
            for (int mt = 0; mt < 4; mt++)
#pragma unroll
                for (int nt = 0; nt < 4; nt++)
                    mma16816(d[mt][nt], afr[mt], bfr[nt]);
        }
    }
}

__global__ __launch_bounds__(256) void syrk_mma_kernel(float* __restrict__ out) {
    const int bi = blockIdx.y, bj = blockIdx.x;
    if (bj < bi) return;
    extern __shared__ __nv_bfloat16 sm[];
    __nv_bfloat16* Ah = sm;
    __nv_bfloat16* Al = Ah + TILE_ELEMS;
    __nv_bfloat16* Bh = Al + TILE_ELEMS;
    __nv_bfloat16* Bl = Bh + TILE_ELEMS;

    const int tid = threadIdx.x;
    const int lane = tid & 31, wid = tid >> 5;
    const int i0 = bi * 128, j0 = bj * 128;
    const int m0 = (wid & 1) * 64, n0 = (wid >> 1) * 32;
    const int g = lane >> 2, tig = lane & 3;

    const uint4* EH = (const uint4*)g_embh;
    const uint4* EL = (const uint4*)g_embl;
#pragma unroll
    for (int e = 0; e < 8; e++) {
        int idx = tid + e * 256;
        int row = idx >> 4, ch = idx & 15;
        *(uint4*)&Ah[row * LDB + ch * 8] = EH[(size_t)(i0 + row) * 16 + ch];
        *(uint4*)&Al[row * LDB + ch * 8] = EL[(size_t)(i0 + row) * 16 + ch];
        *(uint4*)&Bh[row * LDB + ch * 8] = EH[(size_t)(j0 + row) * 16 + ch];
        *(uint4*)&Bl[row * LDB + ch * 8] = EL[(size_t)(j0 + row) * 16 + ch];
    }
    __syncthreads();

    float d[4][4][4];
#pragma unroll
    for (int mt = 0; mt < 4; mt++)
#pragma unroll
        for (int nt = 0; nt < 4; nt++)
#pragma unroll
            for (int q = 0; q < 4; q++) d[mt][nt][q] = 0.f;

    syrk_mma_phase(Ah, Al, Bh, Bl, m0, n0, lane, d);

#pragma unroll
    for (int mt = 0; mt < 4; mt++) {
        int r0 = i0 + m0 + mt * 16 + g;
#pragma unroll
        for (int nt = 0; nt < 4; nt++) {
            int c0 = j0 + n0 + nt * 8 + tig * 2;
            *(float2*)&out[(size_t)r0 * NROWS + c0] = make_float2(d[mt][nt][0], d[mt][nt][1]);
            *(float2*)&out[(size_t)(r0 + 8) * NROWS + c0] = make_float2(d[mt][nt][2], d[mt][nt][3]);
        }
    }

    if (bi != bj) {
#pragma unroll
        for (int mt = 0; mt < 4; mt++)
#pragma unroll
            for (int nt = 0; nt < 4; nt++)
#pragma unroll
                for (int q = 0; q < 4; q++) d[mt][nt][q] = 0.f;

        syrk_mma_phase(Bh, Bl, Ah, Al, m0, n0, lane, d);

#pragma unroll
        for (int mt = 0; mt < 4; mt++) {
            int r0 = j0 + m0 + mt * 16 + g;
#pragma unroll
            for (int nt = 0; nt < 4; nt++) {
                int c0 = i0 + n0 + nt * 8 + tig * 2;
                *(float2*)&out[(size_t)r0 * NROWS + c0] = make_float2(d[mt][nt][0], d[mt][nt][1]);
                *(float2*)&out[(size_t)(r0 + 8) * NROWS + c0] = make_float2(d[mt][nt][2], d[mt][nt][3]);
            }
        }
    }
}

// ---------------- 6. encoder: gates = x @ enc_W_ih.T, LSTM fused ----------------
__global__ __launch_bounds__(256) void enc_fused(const float* __restrict__ x,
                                                 const float* __restrict__ W,
                                                 const float* __restrict__ b_ih,
                                                 const float* __restrict__ b_hh) {
    __shared__ float As[16][128];
    __shared__ float Ws[16][257];
    __shared__ float gsm[16][256];
    const int i0 = blockIdx.x * 16;
    const int tid = threadIdx.x;
    const int n = tid;

    for (int idx = tid; idx < 16 * 128; idx += 256)
        As[idx >> 7][idx & 127] = x[(size_t)(i0 + (idx >> 7)) * 128 + (idx & 127)];

    float acc[16];
#pragma unroll
    for (int r = 0; r < 16; r++) acc[r] = 0.f;

    for (int kt = 0; kt < 128; kt += 16) {
        __syncthreads();
        for (int f = tid; f < 16 * 256; f += 256) {
            int n2 = f >> 4, kk = f & 15;
            Ws[kk][n2] = W[(size_t)n2 * 128 + kt + kk];
        }
        __syncthreads();
#pragma unroll
        for (int kk = 0; kk < 16; kk++) {
            float b = Ws[kk][n];
#pragma unroll
            for (int r = 0; r < 16; r++) acc[r] += As[r][kt + kk] * b;
        }
    }
    __syncthreads();
#pragma unroll
    for (int r = 0; r < 16; r++) gsm[r][n] = acc[r];
    __syncthreads();

#pragma unroll
    for (int e = 0; e < 4; e++) {
        int idx = tid + e * 256;
        int row = idx >> 6, hh = idx & 63;
        float gi = gsm[row][hh] + b_ih[hh] + b_hh[hh];
        float gg = gsm[row][128 + hh] + b_ih[128 + hh] + b_hh[128 + hh];
        float go = gsm[row][192 + hh] + b_ih[192 + hh] + b_hh[192 + hh];
        float c = sigmoidf_(gi) * tanhf(gg);
        g_henc[(size_t)(i0 + row) * 64 + hh] = sigmoidf_(go) * tanhf(c);
    }
}

// ---------------- 7. decoder: gates = h_enc @ dec_W_ih.T, LSTM fused ----------------
__global__ __launch_bounds__(512) void dec_fused(const float* __restrict__ W,
                                                 const float* __restrict__ b_ih,
                                                 const float* __restrict__ b_hh,
                                                 float* __restrict__ out) {
    __shared__ union {
        struct { float As[16][64]; float Ws[16][513]; } in;
        float gsm[16][512];
    } sm;
    const int i0 = blockIdx.x * 16;
    const int tid = threadIdx.x;
    const int n = tid;

    for (int idx = tid; idx < 16 * 64; idx += 512)
        sm.in.As[idx >> 6][idx & 63] = g_henc[(size_t)(i0 + (idx >> 6)) * 64 + (idx & 63)];

    float acc[16];
#pragma unroll
    for (int r = 0; r < 16; r++) acc[r] = 0.f;

    for (int kt = 0; kt < 64; kt += 16) {
        __syncthreads();
        for (int f = tid; f < 16 * 512; f += 512) {
            int n2 = f >> 4, kk = f & 15;
            sm.in.Ws[kk][n2] = W[(size_t)n2 * 64 + kt + kk];
        }
        __syncthreads();
#pragma unroll
        for (int kk = 0; kk < 16; kk++) {
            float b = sm.in.Ws[kk][n];
#pragma unroll
            for (int r = 0; r < 16; r++) acc[r] += sm.in.As[r][kt + kk] * b;
        }
    }
    __syncthreads();
#pragma unroll
    for (int r = 0; r < 16; r++) sm.gsm[r][n] = acc[r];
    __syncthreads();

#pragma unroll
    for (int e = 0; e < 4; e++) {
        int idx = tid + e * 512;
        int row = idx >> 7, hh = idx & 127;
        float gi = sm.gsm[row][hh] + b_ih[hh] + b_hh[hh];
        float gg = sm.gsm[row][256 + hh] + b_ih[256 + hh] + b_hh[256 + hh];
        float go = sm.gsm[row][384 + hh] + b_ih[384 + hh] + b_hh[384 + hh];
        float c = sigmoidf_(gi) * tanhf(gg);
        out[(size_t)(i0 + row) * 128 + hh] = sigmoidf_(go) * tanhf(c);
    }
}

// ---------------- launch ----------------
extern "C" void kernel_launch(void* const* d_in, const int* in_sizes, int n_in,
                              void* d_out, int out_size) {
    const float* x = (const float*)d_in[0];
    const float* adj = (const float*)d_in[1];
    const float* fea_W = (const float*)d_in[2];
    const float* fea_b = (const float*)d_in[3];
    const float* gat_W = (const float*)d_in[4];
    const float* gat_a = (const float*)d_in[5];
    const float* enc_W_ih = (const float*)d_in[6];
    const float* enc_b_ih = (const float*)d_in[8];
    const float* enc_b_hh = (const float*)d_in[9];
    const float* dec_W_ih = (const float*)d_in[10];
    const float* dec_b_ih = (const float*)d_in[12];
    const float* dec_b_hh = (const float*)d_in[13];

    float* out = (float*)d_out;
    float* con_adj = out;
    float* att_adj = out + (size_t)NROWS * NROWS;

    cudaFuncSetAttribute(attn_mma_kernel, cudaFuncAttributeMaxDynamicSharedMemorySize, ATTN_SMEM);
    cudaFuncSetAttribute(syrk_mma_kernel, cudaFuncAttributeMaxDynamicSharedMemorySize, SYRK_SMEM);

    struct_kernel<<<NROWS / 16, 256>>>(x, fea_W, fea_b);                    // 1
    wh_s1s2_kernel<<<NROWS / 16, 256>>>(gat_W, gat_a);                      // 2
    vec_kernel<<<NROWS / 256, 256>>>();                                     // 3
    attn_mma_kernel<<<dim3(NROWS / 64, NSPLIT), 256, ATTN_SMEM>>>(adj);     // 4  <- ncu slot
    combine_kernel<<<NROWS * 32 / 256, 256>>>();                            // 5
    syrk_mma_kernel<<<dim3(64, 64), 256, SYRK_SMEM>>>(con_adj);             // 6
    enc_fused<<<NROWS / 16, 256>>>(x, enc_W_ih, enc_b_ih, enc_b_hh);        // 7
    dec_fused<<<NROWS / 16, 512>>>(dec_W_ih, dec_b_ih, dec_b_hh, att_adj);  // 8
}

// round 17
// speedup vs baseline: 1.1447x; 1.0055x over previous
#include <cuda_runtime.h>
#include <cuda_bf16.h>
#include <cstdint>

#define NROWS 8192
#define IN_DIM 128
#define HID 64
#define NSPLIT 16
#define JSEG (NROWS / NSPLIT)

typedef unsigned long long ull;

// ---------------- scratch (static device globals; no allocation) ----------------
__device__ __align__(16) float g_struct[NROWS * HID];
__device__ __align__(16) __nv_bfloat16 g_Whh[NROWS * IN_DIM];
__device__ __align__(16) __nv_bfloat16 g_Whl[NROWS * IN_DIM];
__device__ __align__(16) float g_s1[NROWS];
__device__ __align__(16) float g_s2[NROWS];
__device__ __align__(16) float g_A[NROWS];
__device__ __align__(16) float g_B[NROWS];
__device__ __align__(16) float g_C[NROWS];
__device__ __align__(16) float g_D[NROWS];
__device__ unsigned g_s2max_bits = 0u;
__device__ __align__(16) float g_henc[NROWS * HID];
__device__ __align__(16) __nv_bfloat16 g_embh[NROWS * IN_DIM];
__device__ __align__(16) __nv_bfloat16 g_embl[NROWS * IN_DIM];
__device__ __align__(16) float g_pacc[NSPLIT * NROWS * IN_DIM];
__device__ __align__(16) float g_pden[NSPLIT * NROWS];

// ---------------- helpers ----------------
__device__ __forceinline__ float sigmoidf_(float x) { return 1.0f / (1.0f + __expf(-x)); }

__device__ __forceinline__ unsigned float_key(float f) {
    unsigned b = __float_as_uint(f);
    return (b & 0x80000000u) ? ~b : (b | 0x80000000u);
}
__device__ __forceinline__ float key_float(unsigned k) {
    unsigned b = (k & 0x80000000u) ? (k & 0x7fffffffu) : ~k;
    return __uint_as_float(b);
}
__device__ __forceinline__ uint32_t smem_u32(const void* p) {
    uint32_t a;
    asm("{ .reg .u64 t; cvta.to.shared.u64 t, %1; cvt.u32.u64 %0, t; }" : "=r"(a) : "l"(p));
    return a;
}

#define CP_ASYNC16(dst, src) asm volatile("cp.async.cg.shared.global [%0], [%1], 16;" :: "r"(dst), "l"(src))
#define CP_COMMIT() asm volatile("cp.async.commit_group;" ::: "memory")
#define CP_WAIT0() asm volatile("cp.async.wait_group 0;" ::: "memory")

// ---------------- mma.sync helpers (bf16, m16n8k16) ----------------
__device__ __forceinline__ void ldm_x4(uint32_t* a, uint32_t addr) {
    asm volatile("ldmatrix.sync.aligned.m8n8.x4.shared.b16 {%0,%1,%2,%3}, [%4];"
                 : "=r"(a[0]), "=r"(a[1]), "=r"(a[2]), "=r"(a[3]) : "r"(addr));
}
__device__ __forceinline__ void ldm_x4t(uint32_t* a, uint32_t addr) {
    asm volatile("ldmatrix.sync.aligned.m8n8.x4.trans.shared.b16 {%0,%1,%2,%3}, [%4];"
                 : "=r"(a[0]), "=r"(a[1]), "=r"(a[2]), "=r"(a[3]) : "r"(addr));
}
__device__ __forceinline__ void ldm_x2(uint32_t* b, uint32_t addr) {
    asm volatile("ldmatrix.sync.aligned.m8n8.x2.shared.b16 {%0,%1}, [%2];"
                 : "=r"(b[0]), "=r"(b[1]) : "r"(addr));
}
__device__ __forceinline__ void mma16816(float* d, const uint32_t* a, const uint32_t* b) {
    asm volatile("mma.sync.aligned.m16n8k16.row.col.f32.bf16.bf16.f32 "
                 "{%0,%1,%2,%3}, {%4,%5,%6,%7}, {%8,%9}, {%0,%1,%2,%3};"
                 : "+f"(d[0]), "+f"(d[1]), "+f"(d[2]), "+f"(d[3])
                 : "r"(a[0]), "r"(a[1]), "r"(a[2]), "r"(a[3]), "r"(b[0]), "r"(b[1]));
}

// ---------------- 1. structure = relu(x @ fea_W + fea_b) ----------------
__global__ __launch_bounds__(256) void struct_kernel(const float* __restrict__ A,
                                                     const float* __restrict__ W,
                                                     const float* __restrict__ bias) {
    __shared__ float As[16][128];
    const int i0 = blockIdx.x * 16;
    const int tid = threadIdx.x;
    const int n = tid & 63, rg = tid >> 6;

    for (int idx = tid; idx < 16 * 128; idx += 256)
        As[idx >> 7][idx & 127] = A[(size_t)(i0 + (idx >> 7)) * 128 + (idx & 127)];
    __syncthreads();

    float acc[4] = {0.f, 0.f, 0.f, 0.f};
#pragma unroll 4
    for (int k = 0; k < 128; k++) {
        float b = W[(size_t)k * 64 + n];
#pragma unroll
        for (int r = 0; r < 4; r++) acc[r] += As[rg * 4 + r][k] * b;
    }
    float bv = bias[n];
#pragma unroll
    for (int r = 0; r < 4; r++)
        g_struct[(size_t)(i0 + rg * 4 + r) * 64 + n] = fmaxf(acc[r] + bv, 0.f);
}

// ---------------- 2. Wh = structure @ gat_W (bf16 hi/lo), fused s1/s2/max(s2) ----------------
__global__ __launch_bounds__(256) void wh_s1s2_kernel(const float* __restrict__ W,
                                                      const float* __restrict__ gat_a) {
    __shared__ float As[16][64];
    __shared__ float r1[8][8], r2[8][8];
    const int i0 = blockIdx.x * 16;
    const int tid = threadIdx.x;
    const int n = tid & 127, rg = tid >> 7;

    for (int idx = tid; idx < 16 * 64; idx += 256)
        As[idx >> 6][idx & 63] = g_struct[(size_t)(i0 + (idx >> 6)) * 64 + (idx & 63)];
    __syncthreads();

    float acc[8];
#pragma unroll
    for (int r = 0; r < 8; r++) acc[r] = 0.f;
#pragma unroll 4
    for (int k = 0; k < 64; k++) {
        float b = W[(size_t)k * 128 + n];
#pragma unroll
        for (int r = 0; r < 8; r++) acc[r] += As[rg * 8 + r][k] * b;
    }
#pragma unroll
    for (int r = 0; r < 8; r++) {
        float v = acc[r];
        __nv_bfloat16 hi = __float2bfloat16(v);
        __nv_bfloat16 lo = __float2bfloat16(v - __bfloat162float(hi));
        g_Whh[(size_t)(i0 + rg * 8 + r) * 128 + n] = hi;
        g_Whl[(size_t)(i0 + rg * 8 + r) * 128 + n] = lo;
    }

    float a1v = gat_a[n], a2v = gat_a[128 + n];
    int warp = tid >> 5, lane = tid & 31;
#pragma unroll
    for (int r = 0; r < 8; r++) {
        float v1 = acc[r] * a1v, v2 = acc[r] * a2v;
#pragma unroll
        for (int off = 16; off; off >>= 1) {
            v1 += __shfl_xor_sync(0xffffffffu, v1, off);
            v2 += __shfl_xor_sync(0xffffffffu, v2, off);
        }
        if (lane == 0) { r1[warp][r] = v1; r2[warp][r] = v2; }
    }
    __syncthreads();
    if (tid < 16) {
        int rgg = tid >> 3, rr = tid & 7;
        float s1 = r1[rgg * 4 + 0][rr] + r1[rgg * 4 + 1][rr] + r1[rgg * 4 + 2][rr] + r1[rgg * 4 + 3][rr];
        float s2 = r2[rgg * 4 + 0][rr] + r2[rgg * 4 + 1][rr] + r2[rgg * 4 + 2][rr] + r2[rgg * 4 + 3][rr];
        g_s1[i0 + tid] = s1;
        g_s2[i0 + tid] = s2;
        float m = s2;
#pragma unroll
        for (int off = 8; off; off >>= 1) m = fmaxf(m, __shfl_xor_sync(0x0000ffffu, m, off));
        if (tid == 0) atomicMax(&g_s2max_bits, float_key(m));
    }
}

// ---------------- 3. precompute A,B,C,D ----------------
__global__ void vec_kernel() {
    int i = blockIdx.x * 256 + threadIdx.x;
    float s2max = key_float(g_s2max_bits);
    float t = g_s1[i] + s2max;
    float m = t > 0.f ? t : 0.2f * t;
    g_A[i] = expf(t - m);
    g_C[i] = expf(0.2f * t - m);
    float u = g_s2[i] - s2max;
    g_B[i] = expf(u);
    g_D[i] = expf(0.2f * u);
}

// ---------------- 4. attention partial: cp.async pipelined mma split-bf16 (measured 179us) ----------------
#define PLD 40
#define WLD 136
#define WHH_OFF(b) ((b) * 8704)
#define WHL_OFF(b) (17408 + (b) * 8704)
#define ADJ_OFF(b) (34816 + (b) * 9216)
#define PH_OFF 53248
#define PL_OFF 58368
#define S2BD_OFF(b) (63488 + (b) * 384)
#define SAC_OFF 64256
#define ATTN_SMEM 65024

__global__ __launch_bounds__(256) void attn_mma_kernel(const float* __restrict__ adj) {
    extern __shared__ __align__(16) char smem[];
    const uint32_t sb = smem_u32(smem);
    float* sac = (float*)(smem + SAC_OFF);   // s1[64], A[64], C[64]

    const int i0 = blockIdx.x * 64;
    const int jb = blockIdx.y * JSEG;
    const int tid = threadIdx.x;
    const int lane = tid & 31, wid = tid >> 5;
    const int wm = wid & 1, wn = wid >> 1;
    if (tid < 64) {
        sac[tid] = g_s1[i0 + tid];
        sac[64 + tid] = g_A[i0 + tid];
        sac[128 + tid] = g_C[i0 + tid];
    }

    const int c4 = (tid & 7) * 4;
    const int rp = tid >> 3;

    float d[2][4][4];
#pragma unroll
    for (int mt = 0; mt < 2; mt++)
#pragma unroll
        for (int nt = 0; nt < 4; nt++)
#pragma unroll
            for (int q = 0; q < 4; q++) d[mt][nt][q] = 0.f;
    float dsum[2] = {0.f, 0.f};

    const int whrow = tid >> 4, whch = tid & 15;
    const int adrow = tid >> 3, adch = tid & 7;

    auto issue_cp = [&](int t) {
        int b = t & 1;
        int jc = jb + t * 32;
#pragma unroll
        for (int e = 0; e < 2; e++) {
            int row = whrow + e * 16;
            CP_ASYNC16(sb + WHH_OFF(b) + row * 272 + whch * 16,
                       (const char*)g_Whh + ((size_t)(jc + row) * 128 + whch * 8) * 2);
            CP_ASYNC16(sb + WHL_OFF(b) + row * 272 + whch * 16,
                       (const char*)g_Whl + ((size_t)(jc + row) * 128 + whch * 8) * 2);
            int arow = adrow + e * 32;
            CP_ASYNC16(sb + ADJ_OFF(b) + arow * 144 + adch * 16,
                       (const char*)adj + ((size_t)(i0 + arow) * NROWS + jc + adch * 4) * 4);
        }
        if (tid < 24) {
            int arr = tid >> 3, sub = tid & 7;
            const float* src = arr == 0 ? g_s2 : (arr == 1 ? g_B : g_D);
            CP_ASYNC16(sb + S2BD_OFF(b) + arr * 128 + sub * 16,
                       (const char*)(src + jc + sub * 4));
        }
    };

    issue_cp(0);
    CP_COMMIT();

    const int T = JSEG / 32;
    for (int t = 0; t < T; t++) {
        const int b = t & 1;
        CP_WAIT0();
        __syncthreads();
        if (t + 1 < T) { issue_cp(t + 1); CP_COMMIT(); }

        // transform: adj smem -> p hi/lo bf16 tiles
        {
            const float* s2bd = (const float*)(smem + S2BD_OFF(b));
            float4 s2v = ((const float4*)s2bd)[tid & 7];
            float4 Bv = ((const float4*)(s2bd + 32))[tid & 7];
            float4 Dv = ((const float4*)(s2bd + 64))[tid & 7];
            const float* adjs = (const float*)(smem + ADJ_OFF(b));
#pragma unroll
            for (int rr = 0; rr < 2; rr++) {
                int r = rp * 2 + rr;
                float4 av = *(const float4*)&adjs[r * 36 + c4];
                float s1 = sac[r], Av = sac[64 + r], Cv = sac[128 + r];
                float pv[4];
                { float tt = s1 + s2v.x; pv[0] = (av.x > 0.f) ? (tt > 0.f ? Av * Bv.x : Cv * Dv.x) : 0.f; }
                { float tt = s1 + s2v.y; pv[1] = (av.y > 0.f) ? (tt > 0.f ? Av * Bv.y : Cv * Dv.y) : 0.f; }
                { float tt = s1 + s2v.z; pv[2] = (av.z > 0.f) ? (tt > 0.f ? Av * Bv.z : Cv * Dv.z) : 0.f; }
                { float tt = s1 + s2v.w; pv[3] = (av.w > 0.f) ? (tt > 0.f ? Av * Bv.w : Cv * Dv.w) : 0.f; }
                ushort4 h4, l4;
                unsigned short* hp = (unsigned short*)&h4;
                unsigned short* lp = (unsigned short*)&l4;
#pragma unroll
                for (int q = 0; q < 4; q++) {
                    __nv_bfloat16 hi = __float2bfloat16(pv[q]);
                    __nv_bfloat16 lo = __float2bfloat16(pv[q] - __bfloat162float(hi));
                    hp[q] = *(unsigned short*)&hi;
                    lp[q] = *(unsigned short*)&lo;
                }
                *(ushort4*)(smem + PH_OFF + (r * PLD + c4) * 2) = h4;
                *(ushort4*)(smem + PL_OFF + (r * PLD + c4) * 2) = l4;
                dsum[rr] += (pv[0] + pv[1]) + (pv[2] + pv[3]);
            }
        }
        __syncthreads();

        // mma: d += ph*Whh + pl*Whh + ph*Whl
        const uint32_t ph_b = sb + PH_OFF, pl_b = sb + PL_OFF;
        const uint32_t whh_b = sb + WHH_OFF(b), whl_b = sb + WHL_OFF(b);
#pragma unroll
        for (int ks = 0; ks < 2; ks++) {
            int k0 = ks * 16;
            uint32_t aph[2][4], apl[2][4], bhh[2][4], bhl[2][4];
#pragma unroll
            for (int mt = 0; mt < 2; mt++) {
                uint32_t off = ((wm * 32 + mt * 16 + (lane & 15)) * PLD + k0 + (lane >> 4) * 8) * 2;
                ldm_x4(aph[mt], ph_b + off);
                ldm_x4(apl[mt], pl_b + off);
            }
#pragma unroll
            for (int np = 0; np < 2; np++) {
                uint32_t off = ((k0 + (lane & 15)) * WLD + wn * 32 + np * 16 + (lane >> 4) * 8) * 2;
                ldm_x4t(bhh[np], whh_b + off);
                ldm_x4t(bhl[np], whl_b + off);
            }
#pragma unroll
            for (int mt = 0; mt < 2; mt++)
#pragma unroll
                for (int np = 0; np < 2; np++)
#pragma unroll
                    for (int h = 0; h < 2; h++) {
                        int nt = np * 2 + h;
                        mma16816(d[mt][nt], aph[mt], &bhh[np][h * 2]);
                        mma16816(d[mt][nt], apl[mt], &bhh[np][h * 2]);
                        mma16816(d[mt][nt], aph[mt], &bhl[np][h * 2]);
                    }
        }
    }

#pragma unroll
    for (int off = 4; off; off >>= 1) {
        dsum[0] += __shfl_down_sync(0xffffffffu, dsum[0], off, 8);
        dsum[1] += __shfl_down_sync(0xffffffffu, dsum[1], off, 8);
    }
    if ((tid & 7) == 0) {
        g_pden[(size_t)blockIdx.y * NROWS + i0 + rp * 2] = dsum[0];
        g_pden[(size_t)blockIdx.y * NROWS + i0 + rp * 2 + 1] = dsum[1];
    }

    float* pa = g_pacc + (size_t)blockIdx.y * NROWS * IN_DIM;
    const int g = lane >> 2, tig = lane & 3;
#pragma unroll
    for (int mt = 0; mt < 2; mt++) {
        int r0 = i0 + wm * 32 + mt * 16 + g;
#pragma unroll
        for (int nt = 0; nt < 4; nt++) {
            int col = wn * 32 + nt * 8 + tig * 2;
            *(float2*)&pa[(size_t)r0 * IN_DIM + col] = make_float2(d[mt][nt][0], d[mt][nt][1]);
            *(float2*)&pa[(size_t)(r0 + 8) * IN_DIM + col] = make_float2(d[mt][nt][2], d[mt][nt][3]);
        }
    }
}

// ---------------- 4b. combine: emb = elu(sum/den), split to bf16 hi+lo ----------------
__global__ __launch_bounds__(256) void combine_kernel() {
    int idx = blockIdx.x * 256 + threadIdx.x;
    int row = idx >> 5;
    float den = 0.f;
    float4 acc = make_float4(0.f, 0.f, 0.f, 0.f);
#pragma unroll
    for (int s = 0; s < NSPLIT; s++) {
        den += g_pden[(size_t)s * NROWS + row];
        float4 v = ((const float4*)g_pacc)[(size_t)s * NROWS * 32 + idx];
        acc.x += v.x; acc.y += v.y; acc.z += v.z; acc.w += v.w;
    }
    float inv = 1.0f / den;
    float o[4] = {acc.x * inv, acc.y * inv, acc.z * inv, acc.w * inv};
    __nv_bfloat16 hi[4], lo[4];
#pragma unroll
    for (int j = 0; j < 4; j++) {
        o[j] = o[j] > 0.f ? o[j] : expm1f(o[j]);
        hi[j] = __float2bfloat16(o[j]);
        lo[j] = __float2bfloat16(o[j] - __bfloat162float(hi[j]));
    }
    *(ull*)&g_embh[(size_t)idx * 4] = *(const ull*)hi;
    *(ull*)&g_embl[(size_t)idx * 4] = *(const ull*)lo;
}

// ---------------- 5. con_adj = emb @ emb.T: 3 MMA passes + transpose-mirror ----------------
#define LDB 136
#define TILE_ELEMS (128 * LDB)
#define SYRK_SMEM (4 * TILE_ELEMS * 2)   // 139264 B; d_s (66560 B) aliases the front
#define DPITCH 130

__device__ __forceinline__ void syrk_mma_phase(
    const __nv_bfloat16* Ah, const __nv_bfloat16* Al,
    const __nv_bfloat16* Bh, const __nv_bfloat16* Bl,
    int m0, int n0, int lane, float d[4][4][4]) {
#pragma unroll
    for (int pass = 0; pass < 3; pass++) {
        const __nv_bfloat16* Ap = (pass == 2) ? Al : Ah;
        const __nv_bfloat16* Bp = (pass == 1) ? Bl : Bh;
        uint32_t a_base = smem_u32(Ap);
        uint32_t b_base = smem_u32(Bp);
#pragma unroll
        for (int ks = 0; ks < 8; ks++) {
            int k0 = ks * 16;
            uint32_t afr[4][4], bfr[4][2];
#pragma unroll
            for (int mt = 0; mt < 4; mt++) {
                int row = m0 + mt * 16 + (lane & 15);
                int col = k0 + (lane >> 4) * 8;
                ldm_x4(afr[mt], a_base + (row * LDB + col) * 2);
            }
#pragma unroll
            for (int nt = 0; nt < 4; nt++) {
                int row = n0 + nt * 8 + (lane & 7);
                int col = k0 + ((lane >> 3) & 1) * 8;
                ldm_x2(bfr[nt], b_base + (row * LDB + col) * 2);
            }
#pragma unroll
            for (int mt = 0; mt < 4; mt++)
#pragma unroll
                for (int nt = 0; nt < 4; nt++)
                    mma16816(d[mt][nt], afr[mt], bfr[nt]);
        }
    }
}

__global__ __launch_bounds__(256) void syrk_mma_kernel(float* __restrict__ out) {
    const int bi = blockIdx.y, bj = blockIdx.x;
    if (bj < bi) return;
    extern __shared__ __nv_bfloat16 sm[];
    __nv_bfloat16* Ah = sm;
    __nv_bfloat16* Al = Ah + TILE_ELEMS;
    __nv_bfloat16* Bh = Al + TILE_ELEMS;
    __nv_bfloat16* Bl = Bh + TILE_ELEMS;
    float* d_s = (float*)sm;   // aliases tiles; used only after MMAs complete

    const int tid = threadIdx.x;
    const int lane = tid & 31, wid = tid >> 5;
    const int i0 = bi * 128, j0 = bj * 128;
    const int m0 = (wid & 1) * 64, n0 = (wid >> 1) * 32;
    const int g = lane >> 2, tig = lane & 3;

    const uint4* EH = (const uint4*)g_embh;
    const uint4* EL = (const uint4*)g_embl;
#pragma unroll
    for (int e = 0; e < 8; e++) {
        int idx = tid + e * 256;
        int row = idx >> 4, ch = idx & 15;
        *(uint4*)&Ah[row * LDB + ch * 8] = EH[(size_t)(i0 + row) * 16 + ch];
        *(uint4*)&Al[row * LDB + ch * 8] = EL[(size_t)(i0 + row) * 16 + ch];
        *(uint4*)&Bh[row * LDB + ch * 8] = EH[(size_t)(j0 + row) * 16 + ch];
        *(uint4*)&Bl[row * LDB + ch * 8] = EL[(size_t)(j0 + row) * 16 + ch];
    }
    __syncthreads();

    float d[4][4][4];
#pragma unroll
    for (int mt = 0; mt < 4; mt++)
#pragma unroll
        for (int nt = 0; nt < 4; nt++)
#pragma unroll
            for (int q = 0; q < 4; q++) d[mt][nt][q] = 0.f;

    syrk_mma_phase(Ah, Al, Bh, Bl, m0, n0, lane, d);

    // normal tile: out[i0.., j0..] directly from fragments
#pragma unroll
    for (int mt = 0; mt < 4; mt++) {
        int r0 = i0 + m0 + mt * 16 + g;
#pragma unroll
        for (int nt = 0; nt < 4; nt++) {
            int c0 = j0 + n0 + nt * 8 + tig * 2;
            *(float2*)&out[(size_t)r0 * NROWS + c0] = make_float2(d[mt][nt][0], d[mt][nt][1]);
            *(float2*)&out[(size_t)(r0 + 8) * NROWS + c0] = make_float2(d[mt][nt][2], d[mt][nt][3]);
        }
    }

    if (bi != bj) {
        // mirror tile via smem transpose (no extra MMA): out[j0+r][i0+c] = D[c][r]
        __syncthreads();   // tiles now dead; safe to overwrite with d_s
#pragma unroll
        for (int mt = 0; mt < 4; mt++) {
            int r0 = m0 + mt * 16 + g;
#pragma unroll
            for (int nt = 0; nt < 4; nt++) {
                int c0 = n0 + nt * 8 + tig * 2;
                *(float2*)&d_s[r0 * DPITCH + c0] = make_float2(d[mt][nt][0], d[mt][nt][1]);
                *(float2*)&d_s[(r0 + 8) * DPITCH + c0] = make_float2(d[mt][nt][2], d[mt][nt][3]);
            }
        }
        __syncthreads();

        // each thread: row rr (2 threads/row), 64 cols, transposed reads
        const int rr = tid >> 1;
        const int half = tid & 1;
        float* orow = out + (size_t)(j0 + rr) * NROWS + i0 + half * 64;
#pragma unroll
        for (int k4 = 0; k4 < 16; k4++) {
            int cc = half * 64 + k4 * 4;
            float4 v = make_float4(d_s[cc * DPITCH + rr],
                                   d_s[(cc + 1) * DPITCH + rr],
                                   d_s[(cc + 2) * DPITCH + rr],
                                   d_s[(cc + 3) * DPITCH + rr]);
            *(float4*)(orow + k4 * 4) = v;
        }
    }
}

// ---------------- 6. encoder: gates = x @ enc_W_ih.T, LSTM fused ----------------
__global__ __launch_bounds__(256) void enc_fused(const float* __restrict__ x,
                                                 const float* __restrict__ W,
                                                 const float* __restrict__ b_ih,
                                                 const float* __restrict__ b_hh) {
    __shared__ float As[16][128];
    __shared__ float Ws[16][257];
    __shared__ float gsm[16][256];
    const int i0 = blockIdx.x * 16;
    const int tid = threadIdx.x;
    const int n = tid;

    for (int idx = tid; idx < 16 * 128; idx += 256)
        As[idx >> 7][idx & 127] = x[(size_t)(i0 + (idx >> 7)) * 128 + (idx & 127)];

    float acc[16];
#pragma unroll
    for (int r = 0; r < 16; r++) acc[r] = 0.f;

    for (int kt = 0; kt < 128; kt += 16) {
        __syncthreads();
        for (int f = tid; f < 16 * 256; f += 256) {
            int n2 = f >> 4, kk = f & 15;
            Ws[kk][n2] = W[(size_t)n2 * 128 + kt + kk];
        }
        __syncthreads();
#pragma unroll
        for (int kk = 0; kk < 16; kk++) {
            float b = Ws[kk][n];
#pragma unroll
            for (int r = 0; r < 16; r++) acc[r] += As[r][kt + kk] * b;
        }
    }
    __syncthreads();
#pragma unroll
    for (int r = 0; r < 16; r++) gsm[r][n] = acc[r];
    __syncthreads();

#pragma unroll
    for (int e = 0; e < 4; e++) {
        int idx = tid + e * 256;
        int row = idx >> 6, hh = idx & 63;
        float gi = gsm[row][hh] + b_ih[hh] + b_hh[hh];
        float gg = gsm[row][128 + hh] + b_ih[128 + hh] + b_hh[128 + hh];
        float go = gsm[row][192 + hh] + b_ih[192 + hh] + b_hh[192 + hh];
        float c = sigmoidf_(gi) * tanhf(gg);
        g_henc[(size_t)(i0 + row) * 64 + hh] = sigmoidf_(go) * tanhf(c);
    }
}

// ---------------- 7. decoder: gates = h_enc @ dec_W_ih.T, LSTM fused ----------------
__global__ __launch_bounds__(512) void dec_fused(const float* __restrict__ W,
                                                 const float* __restrict__ b_ih,
                                                 const float* __restrict__ b_hh,
                                                 float* __restrict__ out) {
    __shared__ union {
        struct { float As[16][64]; float Ws[16][513]; } in;
        float gsm[16][512];
    } sm;
    const int i0 = blockIdx.x * 16;
    const int tid = threadIdx.x;
    const int n = tid;

    for (int idx = tid; idx < 16 * 64; idx += 512)
        sm.in.As[idx >> 6][idx & 63] = g_henc[(size_t)(i0 + (idx >> 6)) * 64 + (idx & 63)];

    float acc[16];
#pragma unroll
    for (int r = 0; r < 16; r++) acc[r] = 0.f;

    for (int kt = 0; kt < 64; kt += 16) {
        __syncthreads();
        for (int f = tid; f < 16 * 512; f += 512) {
            int n2 = f >> 4, kk = f & 15;
            sm.in.Ws[kk][n2] = W[(size_t)n2 * 64 + kt + kk];
        }
        __syncthreads();
#pragma unroll
        for (int kk = 0; kk < 16; kk++) {
            float b = sm.in.Ws[kk][n];
#pragma unroll
            for (int r = 0; r < 16; r++) acc[r] += sm.in.As[r][kt + kk] * b;
        }
    }
    __syncthreads();
#pragma unroll
    for (int r = 0; r < 16; r++) sm.gsm[r][n] = acc[r];
    __syncthreads();

#pragma unroll
    for (int e = 0; e < 4; e++) {
        int idx = tid + e * 512;
        int row = idx >> 7, hh = idx & 127;
        float gi = sm.gsm[row][hh] + b_ih[hh] + b_hh[hh];
        float gg = sm.gsm[row][256 + hh] + b_ih[256 + hh] + b_hh[256 + hh];
        float go = sm.gsm[row][384 + hh] + b_ih[384 + hh] + b_hh[384 + hh];
        float c = sigmoidf_(gi) * tanhf(gg);
        out[(size_t)(i0 + row) * 128 + hh] = sigmoidf_(go) * tanhf(c);
    }
}

// ---------------- launch ----------------
extern "C" void kernel_launch(void* const* d_in, const int* in_sizes, int n_in,
                              void* d_out, int out_size) {
    const float* x = (const float*)d_in[0];
    const float* adj = (const float*)d_in[1];
    const float* fea_W = (const float*)d_in[2];
    const float* fea_b = (const float*)d_in[3];
    const float* gat_W = (const float*)d_in[4];
    const float* gat_a = (const float*)d_in[5];
    const float* enc_W_ih = (const float*)d_in[6];
    const float* enc_b_ih = (const float*)d_in[8];
    const float* enc_b_hh = (const float*)d_in[9];
    const float* dec_W_ih = (const float*)d_in[10];
    const float* dec_b_ih = (const float*)d_in[12];
    const float* dec_b_hh = (const float*)d_in[13];

    float* out = (float*)d_out;
    float* con_adj = out;
    float* att_adj = out + (size_t)NROWS * NROWS;

    cudaFuncSetAttribute(attn_mma_kernel, cudaFuncAttributeMaxDynamicSharedMemorySize, ATTN_SMEM);
    cudaFuncSetAttribute(syrk_mma_kernel, cudaFuncAttributeMaxDynamicSharedMemorySize, SYRK_SMEM);

    struct_kernel<<<NROWS / 16, 256>>>(x, fea_W, fea_b);                    // 1
    wh_s1s2_kernel<<<NROWS / 16, 256>>>(gat_W, gat_a);                      // 2
    vec_kernel<<<NROWS / 256, 256>>>();                                     // 3
    attn_mma_kernel<<<dim3(NROWS / 64, NSPLIT), 256, ATTN_SMEM>>>(adj);     // 4  <- ncu slot
    combine_kernel<<<NROWS * 32 / 256, 256>>>();                            // 5
    syrk_mma_kernel<<<dim3(64, 64), 256, SYRK_SMEM>>>(con_adj);             // 6
    enc_fused<<<NROWS / 16, 256>>>(x, enc_W_ih, enc_b_ih, enc_b_hh);        // 7
    dec_fused<<<NROWS / 16, 512>>>(dec_W_ih, dec_b_ih, dec_b_hh, att_adj);  // 8
}